// round 2
// baseline (speedup 1.0000x reference)
#include <cuda_runtime.h>
#include <math.h>

#define D 768
#define E 8
#define F 3072
#define T_TOK 4096

// ---- scratch (no cudaMalloc allowed) ----
__device__ int   g_counts[E];
__device__ int   g_list[E * T_TOK];
__device__ float g_gates[E * T_TOK];
__device__ float g_H[(size_t)E * T_TOK * F];   // per-expert hidden activations

__global__ void init_kernel() {
    if (threadIdx.x < E) g_counts[threadIdx.x] = 0;
}

// One block per token. 8 warps: warp w computes gate/noise logits for expert w.
__global__ void router_kernel(const float* __restrict__ x,
                              const float* __restrict__ noise,
                              const float* __restrict__ Wg, const float* __restrict__ bg,
                              const float* __restrict__ Wn, const float* __restrict__ bn) {
    int t   = blockIdx.x;
    int tid = threadIdx.x;
    int w   = tid >> 5, lane = tid & 31;

    __shared__ float xs[D];
    __shared__ float noisy[E];

    const float* xr = x + (size_t)t * D;
    for (int i = tid; i < D; i += 256) xs[i] = xr[i];
    __syncthreads();

    float sg = 0.f, sn = 0.f;
    for (int i = lane; i < D; i += 32) {
        float xv = xs[i];
        sg += xv * Wg[i * E + w];
        sn += xv * Wn[i * E + w];
    }
    #pragma unroll
    for (int o = 16; o > 0; o >>= 1) {
        sg += __shfl_down_sync(0xffffffffu, sg, o);
        sn += __shfl_down_sync(0xffffffffu, sn, o);
    }
    if (lane == 0) {
        float lg = sg + bg[w];
        float ln = sn + bn[w];
        float sp = (ln > 20.f) ? ln : log1pf(expf(ln));   // softplus
        noisy[w] = lg + noise[(size_t)t * E + w] * sp;
    }
    __syncthreads();

    if (tid == 0) {
        // top-2 (first-occurrence tie-break, matches lax.top_k)
        int i1 = 0; float v1 = noisy[0];
        #pragma unroll
        for (int e = 1; e < E; e++) if (noisy[e] > v1) { v1 = noisy[e]; i1 = e; }
        int i2 = -1; float v2 = -3.4e38f;
        #pragma unroll
        for (int e = 0; e < E; e++) {
            if (e == i1) continue;
            if (noisy[e] > v2) { v2 = noisy[e]; i2 = e; }
        }
        // softmax over the two kept logits (others are -inf)
        float eb = expf(v2 - v1);
        float p1 = 1.f / (1.f + eb);
        float p2 = eb  / (1.f + eb);
        if (p1 > 1e-9f) {
            int pos = atomicAdd(&g_counts[i1], 1);
            g_list [i1 * T_TOK + pos] = t;
            g_gates[i1 * T_TOK + pos] = p1;
        }
        if (p2 > 1e-9f) {
            int pos = atomicAdd(&g_counts[i2], 1);
            g_list [i2 * T_TOK + pos] = t;
            g_gates[i2 * T_TOK + pos] = p2;
        }
    }
}

// Stage 1: H[e, m, :] = relu(x[tok_m] @ W1[e] + b1[e]).  Gathered-row GEMM.
// 64x64 tile, K-step 16, 256 threads, 4x4 per-thread register tile.
__global__ void __launch_bounds__(256) expert_gemm1(const float* __restrict__ x,
                                                    const float* __restrict__ W1,
                                                    const float* __restrict__ b1) {
    int e   = blockIdx.z;
    int cnt = g_counts[e];
    int m0  = blockIdx.y * 64;
    if (m0 >= cnt) return;
    int n0  = blockIdx.x * 64;

    __shared__ __align__(16) float As[16][64];
    __shared__ __align__(16) float Bs[16][64];
    __shared__ int toks[64];

    int tid = threadIdx.x;
    if (tid < 64) {
        int m = m0 + tid;
        toks[tid] = (m < cnt) ? g_list[e * T_TOK + m] : -1;
    }
    __syncthreads();

    int tx = tid & 15, ty = tid >> 4;
    float acc[4][4];
    #pragma unroll
    for (int i = 0; i < 4; i++)
        #pragma unroll
        for (int j = 0; j < 4; j++) acc[i][j] = 0.f;

    const float* Bb = W1 + (size_t)e * D * F;

    for (int k0 = 0; k0 < D; k0 += 16) {
        #pragma unroll
        for (int i = 0; i < 4; i++) {
            int idx = tid + i * 256;
            int k = idx & 15, m = idx >> 4;
            int tok = toks[m];
            As[k][m] = (tok >= 0) ? x[(size_t)tok * D + k0 + k] : 0.f;
        }
        #pragma unroll
        for (int i = 0; i < 4; i++) {
            int idx = tid + i * 256;
            int n = idx & 63, k = idx >> 6;
            Bs[k][n] = Bb[(size_t)(k0 + k) * F + n0 + n];
        }
        __syncthreads();
        #pragma unroll
        for (int k = 0; k < 16; k++) {
            float4 a = *(const float4*)&As[k][ty * 4];
            float4 b = *(const float4*)&Bs[k][tx * 4];
            float av[4] = {a.x, a.y, a.z, a.w};
            float bv[4] = {b.x, b.y, b.z, b.w};
            #pragma unroll
            for (int i = 0; i < 4; i++)
                #pragma unroll
                for (int j = 0; j < 4; j++)
                    acc[i][j] = fmaf(av[i], bv[j], acc[i][j]);
        }
        __syncthreads();
    }

    float bb[4];
    #pragma unroll
    for (int j = 0; j < 4; j++) bb[j] = b1[(size_t)e * F + n0 + tx * 4 + j];

    #pragma unroll
    for (int i = 0; i < 4; i++) {
        int m = m0 + ty * 4 + i;
        if (m < cnt) {
            float* Hp = &g_H[((size_t)e * T_TOK + m) * F + n0 + tx * 4];
            #pragma unroll
            for (int j = 0; j < 4; j++)
                Hp[j] = fmaxf(acc[i][j] + bb[j], 0.f);
        }
    }
}

// Stage 2: out[tok] += gate * (H[e, m, :] @ W2[e] + b2[e])
__global__ void __launch_bounds__(256) expert_gemm2(const float* __restrict__ W2,
                                                    const float* __restrict__ b2,
                                                    float* __restrict__ out) {
    int e   = blockIdx.z;
    int cnt = g_counts[e];
    int m0  = blockIdx.y * 64;
    if (m0 >= cnt) return;
    int n0  = blockIdx.x * 64;

    __shared__ __align__(16) float As[16][64];
    __shared__ __align__(16) float Bs[16][64];

    int tid = threadIdx.x;
    int tx = tid & 15, ty = tid >> 4;
    float acc[4][4];
    #pragma unroll
    for (int i = 0; i < 4; i++)
        #pragma unroll
        for (int j = 0; j < 4; j++) acc[i][j] = 0.f;

    const float* Bb = W2 + (size_t)e * F * D;

    for (int k0 = 0; k0 < F; k0 += 16) {
        #pragma unroll
        for (int i = 0; i < 4; i++) {
            int idx = tid + i * 256;
            int k = idx & 15, m = idx >> 4;
            As[k][m] = (m0 + m < cnt)
                ? g_H[((size_t)e * T_TOK + m0 + m) * F + k0 + k] : 0.f;
        }
        #pragma unroll
        for (int i = 0; i < 4; i++) {
            int idx = tid + i * 256;
            int n = idx & 63, k = idx >> 6;
            Bs[k][n] = Bb[(size_t)(k0 + k) * D + n0 + n];
        }
        __syncthreads();
        #pragma unroll
        for (int k = 0; k < 16; k++) {
            float4 a = *(const float4*)&As[k][ty * 4];
            float4 b = *(const float4*)&Bs[k][tx * 4];
            float av[4] = {a.x, a.y, a.z, a.w};
            float bv[4] = {b.x, b.y, b.z, b.w};
            #pragma unroll
            for (int i = 0; i < 4; i++)
                #pragma unroll
                for (int j = 0; j < 4; j++)
                    acc[i][j] = fmaf(av[i], bv[j], acc[i][j]);
        }
        __syncthreads();
    }

    #pragma unroll
    for (int i = 0; i < 4; i++) {
        int m = m0 + ty * 4 + i;
        if (m >= cnt) continue;
        int   tok = g_list [e * T_TOK + m];
        float g   = g_gates[e * T_TOK + m];
        #pragma unroll
        for (int j = 0; j < 4; j++) {
            int n = n0 + tx * 4 + j;
            float v = g * (acc[i][j] + b2[(size_t)e * D + n]);
            atomicAdd(&out[(size_t)tok * D + n], v);
        }
    }
}

extern "C" void kernel_launch(void* const* d_in, const int* in_sizes, int n_in,
                              void* d_out, int out_size) {
    const float* x     = (const float*)d_in[0];
    const float* noise = (const float*)d_in[1];
    const float* Wg    = (const float*)d_in[2];
    const float* bg    = (const float*)d_in[3];
    const float* Wn    = (const float*)d_in[4];
    const float* bn    = (const float*)d_in[5];
    const float* W1    = (const float*)d_in[6];
    const float* b1    = (const float*)d_in[7];
    const float* W2    = (const float*)d_in[8];
    const float* b2    = (const float*)d_in[9];
    float* out = (float*)d_out;

    cudaMemsetAsync(out, 0, (size_t)out_size * sizeof(float));
    init_kernel<<<1, 32>>>();
    router_kernel<<<T_TOK, 256>>>(x, noise, Wg, bg, Wn, bn);
    expert_gemm1<<<dim3(F / 64, T_TOK / 64, E), 256>>>(x, W1, b1);
    expert_gemm2<<<dim3(D / 64, T_TOK / 64, E), 256>>>(W2, b2, out);
}

// round 4
// speedup vs baseline: 3.0251x; 3.0251x over previous
#include <cuda_runtime.h>
#include <cuda_bf16.h>
#include <math.h>
#include <stdint.h>

#define D 768
#define E 8
#define F 3072
#define T_TOK 4096
#define MAXROWS 10240

typedef __nv_bfloat16 bf16;

__device__ int   g_counts[E];
__device__ int   g_off[E + 1];
__device__ int   g_list[E * T_TOK];
__device__ float g_gates[E * T_TOK];
__device__ bf16  g_Ah[(size_t)MAXROWS * D];
__device__ bf16  g_Al[(size_t)MAXROWS * D];
__device__ bf16  g_Hh[(size_t)MAXROWS * F];
__device__ bf16  g_Hl[(size_t)MAXROWS * F];
__device__ bf16  g_W1h[(size_t)E * D * F];   // [E][F][D] K-major
__device__ bf16  g_W1l[(size_t)E * D * F];
__device__ bf16  g_W2h[(size_t)E * D * F];   // [E][D][F] K-major
__device__ bf16  g_W2l[(size_t)E * D * F];

__device__ __forceinline__ uint32_t smem_u32(const void* p) {
    uint32_t a;
    asm("{ .reg .u64 t; cvta.to.shared.u64 t, %1; cvt.u32.u64 %0, t; }" : "=r"(a) : "l"(p));
    return a;
}
__device__ __forceinline__ void cp16(uint32_t dst, const void* src) {
    asm volatile("cp.async.cg.shared.global [%0], [%1], 16;"
                 :: "r"(dst), "l"(__cvta_generic_to_global(src)));
}
#define CP_COMMIT() asm volatile("cp.async.commit_group;" ::: "memory")

__device__ __forceinline__ void ldm_x4(uint32_t* r, uint32_t addr) {
    asm volatile("ldmatrix.sync.aligned.m8n8.x4.shared.b16 {%0,%1,%2,%3}, [%4];"
                 : "=r"(r[0]), "=r"(r[1]), "=r"(r[2]), "=r"(r[3]) : "r"(addr));
}
__device__ __forceinline__ void mma_bf16(float* c, const uint32_t* a, uint32_t b0, uint32_t b1) {
    asm volatile("mma.sync.aligned.m16n8k16.row.col.f32.bf16.bf16.f32 "
                 "{%0,%1,%2,%3}, {%4,%5,%6,%7}, {%8,%9}, {%0,%1,%2,%3};"
                 : "+f"(c[0]), "+f"(c[1]), "+f"(c[2]), "+f"(c[3])
                 : "r"(a[0]), "r"(a[1]), "r"(a[2]), "r"(a[3]), "r"(b0), "r"(b1));
}

__device__ __forceinline__ void split_bf16(float v, bf16& hi, bf16& lo) {
    hi = __float2bfloat16_rn(v);
    lo = __float2bfloat16_rn(v - __bfloat162float(hi));
}

__global__ void init_kernel() { if (threadIdx.x < E) g_counts[threadIdx.x] = 0; }

__global__ void router_kernel(const float* __restrict__ x, const float* __restrict__ noise,
                              const float* __restrict__ Wg, const float* __restrict__ bg,
                              const float* __restrict__ Wn, const float* __restrict__ bn) {
    int t = blockIdx.x, tid = threadIdx.x, w = tid >> 5, lane = tid & 31;
    __shared__ float xs[D];
    __shared__ float noisy[E];
    const float* xr = x + (size_t)t * D;
    for (int i = tid; i < D; i += 256) xs[i] = xr[i];
    __syncthreads();
    float sg = 0.f, sn = 0.f;
    for (int i = lane; i < D; i += 32) {
        float xv = xs[i];
        sg += xv * Wg[i * E + w];
        sn += xv * Wn[i * E + w];
    }
    #pragma unroll
    for (int o = 16; o > 0; o >>= 1) {
        sg += __shfl_down_sync(~0u, sg, o);
        sn += __shfl_down_sync(~0u, sn, o);
    }
    if (lane == 0) {
        float lg = sg + bg[w], ln = sn + bn[w];
        float sp = (ln > 20.f) ? ln : log1pf(expf(ln));
        noisy[w] = lg + noise[(size_t)t * E + w] * sp;
    }
    __syncthreads();
    if (tid == 0) {
        int i1 = 0; float v1 = noisy[0];
        #pragma unroll
        for (int e = 1; e < E; e++) if (noisy[e] > v1) { v1 = noisy[e]; i1 = e; }
        int i2 = -1; float v2 = -3.4e38f;
        #pragma unroll
        for (int e = 0; e < E; e++) {
            if (e == i1) continue;
            if (noisy[e] > v2) { v2 = noisy[e]; i2 = e; }
        }
        float eb = expf(v2 - v1);
        float p1 = 1.f / (1.f + eb), p2 = eb / (1.f + eb);
        if (p1 > 1e-9f) {
            int pos = atomicAdd(&g_counts[i1], 1);
            g_list[i1 * T_TOK + pos] = t; g_gates[i1 * T_TOK + pos] = p1;
        }
        if (p2 > 1e-9f) {
            int pos = atomicAdd(&g_counts[i2], 1);
            g_list[i2 * T_TOK + pos] = t; g_gates[i2 * T_TOK + pos] = p2;
        }
    }
}

__global__ void finalize_kernel() {
    if (threadIdx.x == 0) {
        int off = 0;
        for (int e = 0; e < E; e++) { g_off[e] = off; off += (g_counts[e] + 127) & ~127; }
        g_off[E] = off;
    }
}

__global__ void gather_split_kernel(const float* __restrict__ x) {
    int e = blockIdx.x, rb = blockIdx.y * 128;
    int cnt = g_counts[e], pad = (cnt + 127) & ~127;
    if (rb >= pad) return;
    int base = g_off[e];
    for (int idx = threadIdx.x; idx < 128 * D; idx += 256) {
        int m = rb + idx / D, k = idx % D;
        float v = (m < cnt) ? x[(size_t)g_list[e * T_TOK + m] * D + k] : 0.f;
        bf16 vh, vl; split_bf16(v, vh, vl);
        size_t o = (size_t)(base + m) * D + k;
        g_Ah[o] = vh; g_Al[o] = vl;
    }
}

// W [E][R][C] f32 -> Th/Tl [E][C][R] bf16
__global__ void transpose_split_kernel(const float* __restrict__ W, int R, int C, int which) {
    __shared__ float t[32][33];
    bf16* Th = which ? g_W2h : g_W1h;
    bf16* Tl = which ? g_W2l : g_W1l;
    int e = blockIdx.z, c0 = blockIdx.x * 32, r0 = blockIdx.y * 32;
    int x = threadIdx.x, y = threadIdx.y;
    const float* Wp = W + (size_t)e * R * C;
    #pragma unroll
    for (int i = 0; i < 4; i++)
        t[y + 8 * i][x] = Wp[(size_t)(r0 + y + 8 * i) * C + c0 + x];
    __syncthreads();
    size_t ob = (size_t)e * C * R;
    #pragma unroll
    for (int i = 0; i < 4; i++) {
        float v = t[x][y + 8 * i];
        bf16 vh, vl; split_bf16(v, vh, vl);
        size_t o = ob + (size_t)(c0 + y + 8 * i) * R + r0 + x;
        Th[o] = vh; Tl[o] = vl;
    }
}

// ------------- mma.sync bf16 split GEMM -------------
// CTA tile 128x128, K-step 32, 8 warps (4M x 2N), warp tile 32x64.
// smem stage: [Ah|Al|Bh|Bl], each 128 rows x 80B pitch (32 bf16 + pad) = 10240B.
#define PITCH 80
#define ARR_B 10240
#define STG_B 40960          // 4 arrays
#define SMEM_DYN 81920       // 2 stages; epilogue (128*132*4=67584) reuses it

template<int KDIM, int NTOT, int EPI>
__global__ void __launch_bounds__(256, 1) moe_gemm_mma(const float* __restrict__ bias,
                                                       float* __restrict__ out) {
    int e = blockIdx.z, cnt = g_counts[e];
    int m0 = blockIdx.y * 128;
    int pad = (cnt + 127) & ~127;
    if (m0 >= pad) return;
    int n0 = blockIdx.x * 128, rowbase = g_off[e];

    extern __shared__ __align__(1024) char smem[];
    uint32_t sb0 = smem_u32(smem);
    int tid = threadIdx.x, wid = tid >> 5, lane = tid & 31;
    int WM = (wid >> 1) * 32, WN = (wid & 1) * 64;

    const bf16* Agh = (EPI == 1 ? g_Ah : g_Hh) + (size_t)(rowbase + m0) * KDIM;
    const bf16* Agl = (EPI == 1 ? g_Al : g_Hl) + (size_t)(rowbase + m0) * KDIM;
    const bf16* Bgh = (EPI == 1 ? g_W1h : g_W2h) + ((size_t)e * NTOT + n0) * KDIM;
    const bf16* Bgl = (EPI == 1 ? g_W1l : g_W2l) + ((size_t)e * NTOT + n0) * KDIM;
    const bf16* gptr[4] = {Agh, Agl, Bgh, Bgl};

    auto load_stage = [&](int s, int k0) {
        uint32_t sb = sb0 + s * STG_B;
        #pragma unroll
        for (int i = 0; i < 8; i++) {
            int c = tid + i * 256;
            int arr = c >> 9, rc = c & 511, row = rc >> 2, ch = rc & 3;
            cp16(sb + arr * ARR_B + row * PITCH + ch * 16,
                 gptr[arr] + (size_t)row * KDIM + k0 + ch * 8);
        }
        CP_COMMIT();
    };

    float acc[2][8][4];
    #pragma unroll
    for (int mi = 0; mi < 2; mi++)
        #pragma unroll
        for (int ni = 0; ni < 8; ni++)
            #pragma unroll
            for (int q = 0; q < 4; q++) acc[mi][ni][q] = 0.f;

    // per-lane ldmatrix offsets
    uint32_t a_off = (uint32_t)((lane & 15) * PITCH + (lane >> 4) * 16);
    uint32_t b_off = (uint32_t)((((lane >> 4) & 1) * 8 + (lane & 7)) * PITCH + ((lane >> 3) & 1) * 16);

    constexpr int NK = KDIM / 32;
    load_stage(0, 0);
    load_stage(1, 32);

    for (int it = 0; it < NK; it++) {
        int s = it & 1;
        if (it + 1 < NK) asm volatile("cp.async.wait_group 1;" ::: "memory");
        else             asm volatile("cp.async.wait_group 0;" ::: "memory");
        __syncthreads();

        uint32_t sA = sb0 + s * STG_B;
        #pragma unroll
        for (int k16 = 0; k16 < 2; k16++) {
            uint32_t ka = sA + k16 * 32;
            uint32_t ah[2][4], al[2][4], bh[4][4], bl[4][4];
            #pragma unroll
            for (int mi = 0; mi < 2; mi++) {
                uint32_t base = ka + (WM + mi * 16) * PITCH + a_off;
                ldm_x4(ah[mi], base);
                ldm_x4(al[mi], base + ARR_B);
            }
            #pragma unroll
            for (int g = 0; g < 4; g++) {
                uint32_t base = ka + 2 * ARR_B + (WN + g * 16) * PITCH + b_off;
                ldm_x4(bh[g], base);
                ldm_x4(bl[g], base + ARR_B);
            }
            #pragma unroll
            for (int mi = 0; mi < 2; mi++)
                #pragma unroll
                for (int g = 0; g < 4; g++) {
                    mma_bf16(acc[mi][2 * g],     ah[mi], bh[g][0], bh[g][1]);
                    mma_bf16(acc[mi][2 * g + 1], ah[mi], bh[g][2], bh[g][3]);
                    mma_bf16(acc[mi][2 * g],     al[mi], bh[g][0], bh[g][1]);
                    mma_bf16(acc[mi][2 * g + 1], al[mi], bh[g][2], bh[g][3]);
                    mma_bf16(acc[mi][2 * g],     ah[mi], bl[g][0], bl[g][1]);
                    mma_bf16(acc[mi][2 * g + 1], ah[mi], bl[g][2], bl[g][3]);
                }
        }
        __syncthreads();
        if (it + 2 < NK) load_stage(s, (it + 2) * 32);
    }
    __syncthreads();

    // ---- epilogue via smem staging, pitch 132 floats ----
    float* epi = (float*)smem;
    const float* bvec = bias + (size_t)e * NTOT + n0;
    int g4 = lane >> 2, t4 = lane & 3;
    #pragma unroll
    for (int mi = 0; mi < 2; mi++) {
        int r0 = WM + mi * 16 + g4;
        float gate0 = 0.f, gate8 = 0.f;
        if (EPI == 2) {
            if (m0 + r0 < cnt)     gate0 = g_gates[e * T_TOK + m0 + r0];
            if (m0 + r0 + 8 < cnt) gate8 = g_gates[e * T_TOK + m0 + r0 + 8];
        }
        #pragma unroll
        for (int ni = 0; ni < 8; ni++) {
            int col = WN + ni * 8 + t4 * 2;
            float b0 = bvec[col], b1 = bvec[col + 1];
            float* a = acc[mi][ni];
            if (EPI == 1) {
                epi[r0 * 132 + col]           = fmaxf(a[0] + b0, 0.f);
                epi[r0 * 132 + col + 1]       = fmaxf(a[1] + b1, 0.f);
                epi[(r0 + 8) * 132 + col]     = fmaxf(a[2] + b0, 0.f);
                epi[(r0 + 8) * 132 + col + 1] = fmaxf(a[3] + b1, 0.f);
            } else {
                epi[r0 * 132 + col]           = (a[0] + b0) * gate0;
                epi[r0 * 132 + col + 1]       = (a[1] + b1) * gate0;
                epi[(r0 + 8) * 132 + col]     = (a[2] + b0) * gate8;
                epi[(r0 + 8) * 132 + col + 1] = (a[3] + b1) * gate8;
            }
        }
    }
    __syncthreads();

    if (EPI == 1) {
        bf16* Hh = g_Hh + (size_t)(rowbase + m0) * F + n0;
        bf16* Hl = g_Hl + (size_t)(rowbase + m0) * F + n0;
        #pragma unroll
        for (int i = 0; i < 16; i++) {
            int c = tid + i * 256;
            int row = c >> 5, q = c & 31;
            float4 v = *(float4*)&epi[row * 132 + q * 4];
            bf16 h[4], l[4];
            split_bf16(v.x, h[0], l[0]);
            split_bf16(v.y, h[1], l[1]);
            split_bf16(v.z, h[2], l[2]);
            split_bf16(v.w, h[3], l[3]);
            *(uint2*)&Hh[(size_t)row * F + q * 4] = *(uint2*)h;
            *(uint2*)&Hl[(size_t)row * F + q * 4] = *(uint2*)l;
        }
    } else {
        #pragma unroll
        for (int i = 0; i < 16; i++) {
            int c = tid + i * 256;
            int row = c >> 5, q = c & 31;
            if (m0 + row < cnt) {
                int tok = g_list[e * T_TOK + m0 + row];
                float4 v = *(float4*)&epi[row * 132 + q * 4];
                float* op = out + (size_t)tok * D + n0 + q * 4;
                atomicAdd(op + 0, v.x);
                atomicAdd(op + 1, v.y);
                atomicAdd(op + 2, v.z);
                atomicAdd(op + 3, v.w);
            }
        }
    }
}

extern "C" void kernel_launch(void* const* d_in, const int* in_sizes, int n_in,
                              void* d_out, int out_size) {
    const float* x     = (const float*)d_in[0];
    const float* noise = (const float*)d_in[1];
    const float* Wg    = (const float*)d_in[2];
    const float* bg    = (const float*)d_in[3];
    const float* Wn    = (const float*)d_in[4];
    const float* bn    = (const float*)d_in[5];
    const float* W1    = (const float*)d_in[6];
    const float* b1    = (const float*)d_in[7];
    const float* W2    = (const float*)d_in[8];
    const float* b2    = (const float*)d_in[9];
    float* out = (float*)d_out;

    static bool attr_set = false;
    if (!attr_set) {
        cudaFuncSetAttribute(moe_gemm_mma<D, F, 1>, cudaFuncAttributeMaxDynamicSharedMemorySize, SMEM_DYN);
        cudaFuncSetAttribute(moe_gemm_mma<F, D, 2>, cudaFuncAttributeMaxDynamicSharedMemorySize, SMEM_DYN);
        attr_set = true;
    }

    cudaMemsetAsync(out, 0, (size_t)out_size * sizeof(float));
    init_kernel<<<1, 32>>>();
    router_kernel<<<T_TOK, 256>>>(x, noise, Wg, bg, Wn, bn);
    finalize_kernel<<<1, 32>>>();
    gather_split_kernel<<<dim3(E, T_TOK / 128), 256>>>(x);
    transpose_split_kernel<<<dim3(F / 32, D / 32, E), dim3(32, 8)>>>(W1, D, F, 0);
    transpose_split_kernel<<<dim3(D / 32, F / 32, E), dim3(32, 8)>>>(W2, F, D, 1);
    moe_gemm_mma<D, F, 1><<<dim3(F / 128, T_TOK / 128, E), 256, SMEM_DYN>>>(b1, out);
    moe_gemm_mma<F, D, 2><<<dim3(D / 128, T_TOK / 128, E), 256, SMEM_DYN>>>(b2, out);
}

// round 5
// speedup vs baseline: 3.5052x; 1.1587x over previous
#include <cuda_runtime.h>
#include <cuda_bf16.h>
#include <math.h>
#include <stdint.h>

#define D 768
#define E 8
#define F 3072
#define T_TOK 4096
#define MAXROWS 10240

typedef __nv_bfloat16 bf16;

__device__ int   g_counts[E];
__device__ int   g_off[E + 1];
__device__ int   g_list[E * T_TOK];
__device__ float g_gates[E * T_TOK];
__device__ bf16  g_Ah[(size_t)MAXROWS * D];
__device__ bf16  g_Al[(size_t)MAXROWS * D];
__device__ bf16  g_Hh[(size_t)MAXROWS * F];
__device__ bf16  g_Hl[(size_t)MAXROWS * F];
__device__ bf16  g_W1h[(size_t)E * D * F];   // [E][D][F]  native [k][n]
__device__ bf16  g_W1l[(size_t)E * D * F];
__device__ bf16  g_W2h[(size_t)E * D * F];   // [E][F][D]  native [k][n]
__device__ bf16  g_W2l[(size_t)E * D * F];

__device__ __forceinline__ uint32_t smem_u32(const void* p) {
    uint32_t a;
    asm("{ .reg .u64 t; cvta.to.shared.u64 t, %1; cvt.u32.u64 %0, t; }" : "=r"(a) : "l"(p));
    return a;
}
__device__ __forceinline__ void cp16(uint32_t dst, const void* src) {
    asm volatile("cp.async.cg.shared.global [%0], [%1], 16;"
                 :: "r"(dst), "l"(__cvta_generic_to_global(src)));
}
#define CP_COMMIT() asm volatile("cp.async.commit_group;" ::: "memory")

__device__ __forceinline__ void ldm_x4(uint32_t* r, uint32_t addr) {
    asm volatile("ldmatrix.sync.aligned.m8n8.x4.shared.b16 {%0,%1,%2,%3}, [%4];"
                 : "=r"(r[0]), "=r"(r[1]), "=r"(r[2]), "=r"(r[3]) : "r"(addr));
}
__device__ __forceinline__ void ldm_x4_t(uint32_t* r, uint32_t addr) {
    asm volatile("ldmatrix.sync.aligned.m8n8.x4.trans.shared.b16 {%0,%1,%2,%3}, [%4];"
                 : "=r"(r[0]), "=r"(r[1]), "=r"(r[2]), "=r"(r[3]) : "r"(addr));
}
__device__ __forceinline__ void mma_bf16(float* c, const uint32_t* a, uint32_t b0, uint32_t b1) {
    asm volatile("mma.sync.aligned.m16n8k16.row.col.f32.bf16.bf16.f32 "
                 "{%0,%1,%2,%3}, {%4,%5,%6,%7}, {%8,%9}, {%0,%1,%2,%3};"
                 : "+f"(c[0]), "+f"(c[1]), "+f"(c[2]), "+f"(c[3])
                 : "r"(a[0]), "r"(a[1]), "r"(a[2]), "r"(a[3]), "r"(b0), "r"(b1));
}
__device__ __forceinline__ void split_bf16(float v, bf16& hi, bf16& lo) {
    hi = __float2bfloat16_rn(v);
    lo = __float2bfloat16_rn(v - __bfloat162float(hi));
}

__global__ void init_kernel() { if (threadIdx.x < E) g_counts[threadIdx.x] = 0; }

__global__ void router_kernel(const float* __restrict__ x, const float* __restrict__ noise,
                              const float* __restrict__ Wg, const float* __restrict__ bg,
                              const float* __restrict__ Wn, const float* __restrict__ bn) {
    int t = blockIdx.x, tid = threadIdx.x, w = tid >> 5, lane = tid & 31;
    __shared__ float xs[D];
    __shared__ float noisy[E];
    const float* xr = x + (size_t)t * D;
    for (int i = tid; i < D; i += 256) xs[i] = xr[i];
    __syncthreads();
    float sg = 0.f, sn = 0.f;
    for (int i = lane; i < D; i += 32) {
        float xv = xs[i];
        sg += xv * Wg[i * E + w];
        sn += xv * Wn[i * E + w];
    }
    #pragma unroll
    for (int o = 16; o > 0; o >>= 1) {
        sg += __shfl_down_sync(~0u, sg, o);
        sn += __shfl_down_sync(~0u, sn, o);
    }
    if (lane == 0) {
        float lg = sg + bg[w], ln = sn + bn[w];
        float sp = (ln > 20.f) ? ln : log1pf(expf(ln));
        noisy[w] = lg + noise[(size_t)t * E + w] * sp;
    }
    __syncthreads();
    if (tid == 0) {
        int i1 = 0; float v1 = noisy[0];
        #pragma unroll
        for (int e = 1; e < E; e++) if (noisy[e] > v1) { v1 = noisy[e]; i1 = e; }
        int i2 = -1; float v2 = -3.4e38f;
        #pragma unroll
        for (int e = 0; e < E; e++) {
            if (e == i1) continue;
            if (noisy[e] > v2) { v2 = noisy[e]; i2 = e; }
        }
        float eb = expf(v2 - v1);
        float p1 = 1.f / (1.f + eb), p2 = eb / (1.f + eb);
        if (p1 > 1e-9f) {
            int pos = atomicAdd(&g_counts[i1], 1);
            g_list[i1 * T_TOK + pos] = t; g_gates[i1 * T_TOK + pos] = p1;
        }
        if (p2 > 1e-9f) {
            int pos = atomicAdd(&g_counts[i2], 1);
            g_list[i2 * T_TOK + pos] = t; g_gates[i2 * T_TOK + pos] = p2;
        }
    }
}

__global__ void finalize_kernel() {
    if (threadIdx.x == 0) {
        int off = 0;
        for (int e = 0; e < E; e++) { g_off[e] = off; off += (g_counts[e] + 127) & ~127; }
        g_off[E] = off;
    }
}

// 16 rows per block, float4 vectorized. grid (E, 256).
__global__ void __launch_bounds__(256) gather_split_kernel(const float* __restrict__ x) {
    int e = blockIdx.x;
    int cnt = g_counts[e], pad = (cnt + 127) & ~127;
    int rb = blockIdx.y * 16;
    if (rb >= pad) return;
    int base = g_off[e];
    const int Q = D / 4;   // 192 float4 per row
    for (int idx = threadIdx.x; idx < 16 * Q; idx += 256) {
        int m = rb + idx / Q, q = idx % Q;
        float4 v = make_float4(0.f, 0.f, 0.f, 0.f);
        if (m < cnt)
            v = *(const float4*)&x[(size_t)g_list[e * T_TOK + m] * D + q * 4];
        bf16 h[4], l[4];
        split_bf16(v.x, h[0], l[0]);
        split_bf16(v.y, h[1], l[1]);
        split_bf16(v.z, h[2], l[2]);
        split_bf16(v.w, h[3], l[3]);
        size_t o = (size_t)(base + m) * D + q * 4;
        *(uint2*)&g_Ah[o] = *(uint2*)h;
        *(uint2*)&g_Al[o] = *(uint2*)l;
    }
}

// Streaming hi/lo split, no transpose. which=0 -> W1, 1 -> W2.
__global__ void __launch_bounds__(256) split_weights_kernel(const float* __restrict__ W, int which) {
    bf16* Th = which ? g_W2h : g_W1h;
    bf16* Tl = which ? g_W2l : g_W1l;
    const size_t n4 = (size_t)E * D * F / 4;
    size_t stride = (size_t)gridDim.x * blockDim.x;
    for (size_t i = (size_t)blockIdx.x * blockDim.x + threadIdx.x; i < n4; i += stride) {
        float4 v = *(const float4*)&W[i * 4];
        bf16 h[4], l[4];
        split_bf16(v.x, h[0], l[0]);
        split_bf16(v.y, h[1], l[1]);
        split_bf16(v.z, h[2], l[2]);
        split_bf16(v.w, h[3], l[3]);
        *(uint2*)&Th[i * 4] = *(uint2*)h;
        *(uint2*)&Tl[i * 4] = *(uint2*)l;
    }
}

// ------------- mma.sync bf16 split GEMM -------------
// CTA tile 128x128, K-step 32, 8 warps (4M x 2N).
// A smem: [Ah|Al] 128 rows x 80B pitch (32 bf16). B smem: [Bh|Bl] 32 k-rows x 272B pitch (128 bf16).
#define A_PITCH 80
#define A_ARR   10240
#define B_PITCH 272
#define B_ARR   8704
#define B_BASE  20480
#define STG_B   37888
#define SMEM_DYN 75776

template<int KDIM, int NTOT, int EPI>
__global__ void __launch_bounds__(256, 1) moe_gemm_mma(const float* __restrict__ bias,
                                                       float* __restrict__ out) {
    int e = blockIdx.z, cnt = g_counts[e];
    int m0 = blockIdx.y * 128;
    int pad = (cnt + 127) & ~127;
    if (m0 >= pad) return;
    int n0 = blockIdx.x * 128, rowbase = g_off[e];

    extern __shared__ __align__(1024) char smem[];
    uint32_t sb0 = smem_u32(smem);
    int tid = threadIdx.x, wid = tid >> 5, lane = tid & 31;
    int WM = (wid >> 1) * 32, WN = (wid & 1) * 64;

    const bf16* Agh = (EPI == 1 ? g_Ah : g_Hh) + (size_t)(rowbase + m0) * KDIM;
    const bf16* Agl = (EPI == 1 ? g_Al : g_Hl) + (size_t)(rowbase + m0) * KDIM;
    const bf16* Bgh = (EPI == 1 ? g_W1h : g_W2h) + (size_t)e * D * F + n0;
    const bf16* Bgl = (EPI == 1 ? g_W1l : g_W2l) + (size_t)e * D * F + n0;
    const bf16* aptr[2] = {Agh, Agl};
    const bf16* bptr[2] = {Bgh, Bgl};

    auto load_stage = [&](int s, int k0) {
        uint32_t sb = sb0 + s * STG_B;
        #pragma unroll
        for (int i = 0; i < 8; i++) {
            int c = tid + i * 256;
            int arr = c >> 9, rc = c & 511;
            if (arr < 2) {   // A: 128 rows x 4 chunks
                int row = rc >> 2, ch = rc & 3;
                cp16(sb + arr * A_ARR + row * A_PITCH + ch * 16,
                     aptr[arr] + (size_t)row * KDIM + k0 + ch * 8);
            } else {         // B: 32 k-rows x 16 chunks
                int k = rc >> 4, ch = rc & 15;
                cp16(sb + B_BASE + (arr - 2) * B_ARR + k * B_PITCH + ch * 16,
                     bptr[arr - 2] + (size_t)(k0 + k) * NTOT + ch * 8);
            }
        }
        CP_COMMIT();
    };

    float acc[2][8][4];
    #pragma unroll
    for (int mi = 0; mi < 2; mi++)
        #pragma unroll
        for (int ni = 0; ni < 8; ni++)
            #pragma unroll
            for (int q = 0; q < 4; q++) acc[mi][ni][q] = 0.f;

    uint32_t a_off = (uint32_t)((lane & 15) * A_PITCH + (lane >> 4) * 16);
    uint32_t b_off = (uint32_t)((lane & 15) * B_PITCH + (lane >> 4) * 16);

    constexpr int NK = KDIM / 32;
    load_stage(0, 0);
    load_stage(1, 32);

    for (int it = 0; it < NK; it++) {
        int s = it & 1;
        if (it + 1 < NK) asm volatile("cp.async.wait_group 1;" ::: "memory");
        else             asm volatile("cp.async.wait_group 0;" ::: "memory");
        __syncthreads();

        uint32_t sA = sb0 + s * STG_B;
        uint32_t sB = sA + B_BASE;
        #pragma unroll
        for (int k16 = 0; k16 < 2; k16++) {
            uint32_t ah[2][4], al[2][4], bh[4][4], bl[4][4];
            #pragma unroll
            for (int mi = 0; mi < 2; mi++) {
                uint32_t base = sA + (WM + mi * 16) * A_PITCH + k16 * 32 + a_off;
                ldm_x4(ah[mi], base);
                ldm_x4(al[mi], base + A_ARR);
            }
            #pragma unroll
            for (int g = 0; g < 4; g++) {
                uint32_t base = sB + k16 * 16 * B_PITCH + (WN + g * 16) * 2 + b_off;
                ldm_x4_t(bh[g], base);
                ldm_x4_t(bl[g], base + B_ARR);
            }
            #pragma unroll
            for (int mi = 0; mi < 2; mi++)
                #pragma unroll
                for (int g = 0; g < 4; g++) {
                    mma_bf16(acc[mi][2 * g],     ah[mi], bh[g][0], bh[g][1]);
                    mma_bf16(acc[mi][2 * g + 1], ah[mi], bh[g][2], bh[g][3]);
                    mma_bf16(acc[mi][2 * g],     al[mi], bh[g][0], bh[g][1]);
                    mma_bf16(acc[mi][2 * g + 1], al[mi], bh[g][2], bh[g][3]);
                    mma_bf16(acc[mi][2 * g],     ah[mi], bl[g][0], bl[g][1]);
                    mma_bf16(acc[mi][2 * g + 1], ah[mi], bl[g][2], bl[g][3]);
                }
        }
        __syncthreads();
        if (it + 2 < NK) load_stage(s, (it + 2) * 32);
    }
    __syncthreads();

    // ---- epilogue via smem staging, pitch 132 floats ----
    float* epi = (float*)smem;
    const float* bvec = bias + (size_t)e * NTOT + n0;
    int g4 = lane >> 2, t4 = lane & 3;
    #pragma unroll
    for (int mi = 0; mi < 2; mi++) {
        int r0 = WM + mi * 16 + g4;
        float gate0 = 0.f, gate8 = 0.f;
        if (EPI == 2) {
            if (m0 + r0 < cnt)     gate0 = g_gates[e * T_TOK + m0 + r0];
            if (m0 + r0 + 8 < cnt) gate8 = g_gates[e * T_TOK + m0 + r0 + 8];
        }
        #pragma unroll
        for (int ni = 0; ni < 8; ni++) {
            int col = WN + ni * 8 + t4 * 2;
            float b0 = bvec[col], b1 = bvec[col + 1];
            float* a = acc[mi][ni];
            if (EPI == 1) {
                epi[r0 * 132 + col]           = fmaxf(a[0] + b0, 0.f);
                epi[r0 * 132 + col + 1]       = fmaxf(a[1] + b1, 0.f);
                epi[(r0 + 8) * 132 + col]     = fmaxf(a[2] + b0, 0.f);
                epi[(r0 + 8) * 132 + col + 1] = fmaxf(a[3] + b1, 0.f);
            } else {
                epi[r0 * 132 + col]           = (a[0] + b0) * gate0;
                epi[r0 * 132 + col + 1]       = (a[1] + b1) * gate0;
                epi[(r0 + 8) * 132 + col]     = (a[2] + b0) * gate8;
                epi[(r0 + 8) * 132 + col + 1] = (a[3] + b1) * gate8;
            }
        }
    }
    __syncthreads();

    if (EPI == 1) {
        bf16* Hh = g_Hh + (size_t)(rowbase + m0) * F + n0;
        bf16* Hl = g_Hl + (size_t)(rowbase + m0) * F + n0;
        #pragma unroll
        for (int i = 0; i < 16; i++) {
            int c = tid + i * 256;
            int row = c >> 5, q = c & 31;
            float4 v = *(float4*)&epi[row * 132 + q * 4];
            bf16 h[4], l[4];
            split_bf16(v.x, h[0], l[0]);
            split_bf16(v.y, h[1], l[1]);
            split_bf16(v.z, h[2], l[2]);
            split_bf16(v.w, h[3], l[3]);
            *(uint2*)&Hh[(size_t)row * F + q * 4] = *(uint2*)h;
            *(uint2*)&Hl[(size_t)row * F + q * 4] = *(uint2*)l;
        }
    } else {
        #pragma unroll
        for (int i = 0; i < 16; i++) {
            int c = tid + i * 256;
            int row = c >> 5, q = c & 31;
            if (m0 + row < cnt) {
                int tok = g_list[e * T_TOK + m0 + row];
                float4 v = *(float4*)&epi[row * 132 + q * 4];
                float* op = out + (size_t)tok * D + n0 + q * 4;
                atomicAdd(op + 0, v.x);
                atomicAdd(op + 1, v.y);
                atomicAdd(op + 2, v.z);
                atomicAdd(op + 3, v.w);
            }
        }
    }
}

extern "C" void kernel_launch(void* const* d_in, const int* in_sizes, int n_in,
                              void* d_out, int out_size) {
    const float* x     = (const float*)d_in[0];
    const float* noise = (const float*)d_in[1];
    const float* Wg    = (const float*)d_in[2];
    const float* bg    = (const float*)d_in[3];
    const float* Wn    = (const float*)d_in[4];
    const float* bn    = (const float*)d_in[5];
    const float* W1    = (const float*)d_in[6];
    const float* b1    = (const float*)d_in[7];
    const float* W2    = (const float*)d_in[8];
    const float* b2    = (const float*)d_in[9];
    float* out = (float*)d_out;

    static bool attr_set = false;
    if (!attr_set) {
        cudaFuncSetAttribute(moe_gemm_mma<D, F, 1>, cudaFuncAttributeMaxDynamicSharedMemorySize, SMEM_DYN);
        cudaFuncSetAttribute(moe_gemm_mma<F, D, 2>, cudaFuncAttributeMaxDynamicSharedMemorySize, SMEM_DYN);
        attr_set = true;
    }

    cudaMemsetAsync(out, 0, (size_t)out_size * sizeof(float));
    init_kernel<<<1, 32>>>();
    router_kernel<<<T_TOK, 256>>>(x, noise, Wg, bg, Wn, bn);
    finalize_kernel<<<1, 32>>>();
    gather_split_kernel<<<dim3(E, 256), 256>>>(x);
    split_weights_kernel<<<4096, 256>>>(W1, 0);
    split_weights_kernel<<<4096, 256>>>(W2, 1);
    moe_gemm_mma<D, F, 1><<<dim3(F / 128, T_TOK / 128, E), 256, SMEM_DYN>>>(b1, out);
    moe_gemm_mma<F, D, 2><<<dim3(D / 128, T_TOK / 128, E), 256, SMEM_DYN>>>(b2, out);
}

// round 6
// speedup vs baseline: 3.6681x; 1.0465x over previous
#include <cuda_runtime.h>
#include <cuda_bf16.h>
#include <math.h>
#include <stdint.h>

#define D 768
#define E 8
#define F 3072
#define T_TOK 4096
#define MAXROWS 10240

typedef __nv_bfloat16 bf16;

__device__ int   g_counts[E];
__device__ int   g_off[E + 1];
__device__ int   g_list[E * T_TOK];
__device__ float g_gates[E * T_TOK];
__device__ bf16  g_Ah[(size_t)MAXROWS * D];
__device__ bf16  g_Al[(size_t)MAXROWS * D];
__device__ bf16  g_Hh[(size_t)MAXROWS * F];
__device__ bf16  g_Hl[(size_t)MAXROWS * F];
__device__ bf16  g_W1h[(size_t)E * D * F];   // [E][D][F] native [k][n]
__device__ bf16  g_W1l[(size_t)E * D * F];
__device__ bf16  g_W2h[(size_t)E * D * F];   // [E][F][D] native [k][n]
__device__ bf16  g_W2l[(size_t)E * D * F];

__device__ __forceinline__ uint32_t smem_u32(const void* p) {
    uint32_t a;
    asm("{ .reg .u64 t; cvta.to.shared.u64 t, %1; cvt.u32.u64 %0, t; }" : "=r"(a) : "l"(p));
    return a;
}
__device__ __forceinline__ void cp16(uint32_t dst, const void* src) {
    asm volatile("cp.async.cg.shared.global [%0], [%1], 16;"
                 :: "r"(dst), "l"(__cvta_generic_to_global(src)));
}
#define CP_COMMIT() asm volatile("cp.async.commit_group;" ::: "memory")

__device__ __forceinline__ void ldm_x4(uint32_t* r, uint32_t addr) {
    asm volatile("ldmatrix.sync.aligned.m8n8.x4.shared.b16 {%0,%1,%2,%3}, [%4];"
                 : "=r"(r[0]), "=r"(r[1]), "=r"(r[2]), "=r"(r[3]) : "r"(addr));
}
__device__ __forceinline__ void ldm_x4_t(uint32_t* r, uint32_t addr) {
    asm volatile("ldmatrix.sync.aligned.m8n8.x4.trans.shared.b16 {%0,%1,%2,%3}, [%4];"
                 : "=r"(r[0]), "=r"(r[1]), "=r"(r[2]), "=r"(r[3]) : "r"(addr));
}
__device__ __forceinline__ void mma_bf16(float* c, const uint32_t* a, uint32_t b0, uint32_t b1) {
    asm volatile("mma.sync.aligned.m16n8k16.row.col.f32.bf16.bf16.f32 "
                 "{%0,%1,%2,%3}, {%4,%5,%6,%7}, {%8,%9}, {%0,%1,%2,%3};"
                 : "+f"(c[0]), "+f"(c[1]), "+f"(c[2]), "+f"(c[3])
                 : "r"(a[0]), "r"(a[1]), "r"(a[2]), "r"(a[3]), "r"(b0), "r"(b1));
}
__device__ __forceinline__ void split_bf16(float v, bf16& hi, bf16& lo) {
    hi = __float2bfloat16_rn(v);
    lo = __float2bfloat16_rn(v - __bfloat162float(hi));
}

__global__ void init_kernel() { if (threadIdx.x < E) g_counts[threadIdx.x] = 0; }

__global__ void router_kernel(const float* __restrict__ x, const float* __restrict__ noise,
                              const float* __restrict__ Wg, const float* __restrict__ bg,
                              const float* __restrict__ Wn, const float* __restrict__ bn) {
    int t = blockIdx.x, tid = threadIdx.x, w = tid >> 5, lane = tid & 31;
    __shared__ float xs[D];
    __shared__ float noisy[E];
    const float* xr = x + (size_t)t * D;
    for (int i = tid; i < D; i += 256) xs[i] = xr[i];
    __syncthreads();
    float sg = 0.f, sn = 0.f;
    for (int i = lane; i < D; i += 32) {
        float xv = xs[i];
        sg += xv * Wg[i * E + w];
        sn += xv * Wn[i * E + w];
    }
    #pragma unroll
    for (int o = 16; o > 0; o >>= 1) {
        sg += __shfl_down_sync(~0u, sg, o);
        sn += __shfl_down_sync(~0u, sn, o);
    }
    if (lane == 0) {
        float lg = sg + bg[w], ln = sn + bn[w];
        float sp = (ln > 20.f) ? ln : log1pf(expf(ln));
        noisy[w] = lg + noise[(size_t)t * E + w] * sp;
    }
    __syncthreads();
    if (tid == 0) {
        int i1 = 0; float v1 = noisy[0];
        #pragma unroll
        for (int e = 1; e < E; e++) if (noisy[e] > v1) { v1 = noisy[e]; i1 = e; }
        int i2 = -1; float v2 = -3.4e38f;
        #pragma unroll
        for (int e = 0; e < E; e++) {
            if (e == i1) continue;
            if (noisy[e] > v2) { v2 = noisy[e]; i2 = e; }
        }
        float eb = expf(v2 - v1);
        float p1 = 1.f / (1.f + eb), p2 = eb / (1.f + eb);
        if (p1 > 1e-9f) {
            int pos = atomicAdd(&g_counts[i1], 1);
            g_list[i1 * T_TOK + pos] = t; g_gates[i1 * T_TOK + pos] = p1;
        }
        if (p2 > 1e-9f) {
            int pos = atomicAdd(&g_counts[i2], 1);
            g_list[i2 * T_TOK + pos] = t; g_gates[i2 * T_TOK + pos] = p2;
        }
    }
}

__global__ void finalize_kernel() {
    if (threadIdx.x == 0) {
        int off = 0;
        for (int e = 0; e < E; e++) { g_off[e] = off; off += (g_counts[e] + 127) & ~127; }
        g_off[E] = off;
    }
}

__global__ void __launch_bounds__(256) gather_split_kernel(const float* __restrict__ x) {
    int e = blockIdx.x;
    int cnt = g_counts[e], pad = (cnt + 127) & ~127;
    int rb = blockIdx.y * 16;
    if (rb >= pad) return;
    int base = g_off[e];
    const int Q = D / 4;
    for (int idx = threadIdx.x; idx < 16 * Q; idx += 256) {
        int m = rb + idx / Q, q = idx % Q;
        float4 v = make_float4(0.f, 0.f, 0.f, 0.f);
        if (m < cnt)
            v = *(const float4*)&x[(size_t)g_list[e * T_TOK + m] * D + q * 4];
        bf16 h[4], l[4];
        split_bf16(v.x, h[0], l[0]);
        split_bf16(v.y, h[1], l[1]);
        split_bf16(v.z, h[2], l[2]);
        split_bf16(v.w, h[3], l[3]);
        size_t o = (size_t)(base + m) * D + q * 4;
        *(uint2*)&g_Ah[o] = *(uint2*)h;
        *(uint2*)&g_Al[o] = *(uint2*)l;
    }
}

__global__ void __launch_bounds__(256) split_weights_kernel(const float* __restrict__ W, int which) {
    bf16* Th = which ? g_W2h : g_W1h;
    bf16* Tl = which ? g_W2l : g_W1l;
    const size_t n4 = (size_t)E * D * F / 4;
    size_t stride = (size_t)gridDim.x * blockDim.x;
    for (size_t i = (size_t)blockIdx.x * blockDim.x + threadIdx.x; i < n4; i += stride) {
        float4 v = *(const float4*)&W[i * 4];
        bf16 h[4], l[4];
        split_bf16(v.x, h[0], l[0]);
        split_bf16(v.y, h[1], l[1]);
        split_bf16(v.z, h[2], l[2]);
        split_bf16(v.w, h[3], l[3]);
        *(uint2*)&Th[i * 4] = *(uint2*)h;
        *(uint2*)&Tl[i * 4] = *(uint2*)l;
    }
}

// ------------- mma.sync bf16 split GEMM -------------
// CTA 128x128, K-step 64, 3 smem stages, 8 warps (4M x 2N), reg-double-buffered frags.
#define A_PITCH 144           // 64 bf16 = 128B + 16 pad (9x16B units, conflict-free)
#define A_ARR   18432         // 128 * 144
#define B_PITCH 272           // 128 bf16 = 256B + 16 pad (17x16B units)
#define B_ARR   17408         // 64 * 272
#define B_BASE  36864         // 2 * A_ARR
#define STG_B   71680         // B_BASE + 2*B_ARR
#define SMEM_DYN 215040       // 3 stages

template<int KDIM, int NTOT, int EPI>
__global__ void __launch_bounds__(256, 1) moe_gemm_mma(const float* __restrict__ bias,
                                                       float* __restrict__ out) {
    int e = blockIdx.z, cnt = g_counts[e];
    int m0 = blockIdx.y * 128;
    int pad = (cnt + 127) & ~127;
    if (m0 >= pad) return;
    int n0 = blockIdx.x * 128, rowbase = g_off[e];

    extern __shared__ __align__(1024) char smem[];
    uint32_t sb0 = smem_u32(smem);
    int tid = threadIdx.x, wid = tid >> 5, lane = tid & 31;
    int WM = (wid >> 1) * 32, WN = (wid & 1) * 64;

    const bf16* Agh = (EPI == 1 ? g_Ah : g_Hh) + (size_t)(rowbase + m0) * KDIM;
    const bf16* Agl = (EPI == 1 ? g_Al : g_Hl) + (size_t)(rowbase + m0) * KDIM;
    const bf16* Bgh = (EPI == 1 ? g_W1h : g_W2h) + (size_t)e * D * F + n0;
    const bf16* Bgl = (EPI == 1 ? g_W1l : g_W2l) + (size_t)e * D * F + n0;
    const bf16* aptr[2] = {Agh, Agl};
    const bf16* bptr[2] = {Bgh, Bgl};

    auto load_stage = [&](int s, int k0) {
        uint32_t sb = sb0 + s * STG_B;
        #pragma unroll
        for (int i = 0; i < 16; i++) {
            int c = tid + i * 256;
            int arr = c >> 10, rc = c & 1023;
            if (arr < 2) {   // A: 128 rows x 8 chunks of 16B
                int row = rc >> 3, ch = rc & 7;
                cp16(sb + arr * A_ARR + row * A_PITCH + ch * 16,
                     aptr[arr] + (size_t)row * KDIM + k0 + ch * 8);
            } else {         // B: 64 k-rows x 16 chunks of 16B
                int k = rc >> 4, ch = rc & 15;
                cp16(sb + B_BASE + (arr - 2) * B_ARR + k * B_PITCH + ch * 16,
                     bptr[arr - 2] + (size_t)(k0 + k) * NTOT + ch * 8);
            }
        }
        CP_COMMIT();
    };

    float acc[2][8][4];
    #pragma unroll
    for (int mi = 0; mi < 2; mi++)
        #pragma unroll
        for (int ni = 0; ni < 8; ni++)
            #pragma unroll
            for (int q = 0; q < 4; q++) acc[mi][ni][q] = 0.f;

    uint32_t a_off = (uint32_t)((lane & 15) * A_PITCH + (lane >> 4) * 16);
    uint32_t b_off = (uint32_t)((lane & 15) * B_PITCH + (lane >> 4) * 16);

    uint32_t ah[2][2][4], al[2][2][4], bh[2][4][4], bl[2][4][4];

    auto ldfrags = [&](int buf, int k16, uint32_t sA, uint32_t sB) {
        #pragma unroll
        for (int mi = 0; mi < 2; mi++) {
            uint32_t base = sA + (WM + mi * 16) * A_PITCH + k16 * 32 + a_off;
            ldm_x4(ah[buf][mi], base);
            ldm_x4(al[buf][mi], base + A_ARR);
        }
        #pragma unroll
        for (int g = 0; g < 4; g++) {
            uint32_t base = sB + k16 * 16 * B_PITCH + (WN + g * 16) * 2 + b_off;
            ldm_x4_t(bh[buf][g], base);
            ldm_x4_t(bl[buf][g], base + B_ARR);
        }
    };
    auto do_mma = [&](int buf) {
        #pragma unroll
        for (int mi = 0; mi < 2; mi++)
            #pragma unroll
            for (int g = 0; g < 4; g++) {
                mma_bf16(acc[mi][2 * g],     ah[buf][mi], bh[buf][g][0], bh[buf][g][1]);
                mma_bf16(acc[mi][2 * g + 1], ah[buf][mi], bh[buf][g][2], bh[buf][g][3]);
                mma_bf16(acc[mi][2 * g],     al[buf][mi], bh[buf][g][0], bh[buf][g][1]);
                mma_bf16(acc[mi][2 * g + 1], al[buf][mi], bh[buf][g][2], bh[buf][g][3]);
                mma_bf16(acc[mi][2 * g],     ah[buf][mi], bl[buf][g][0], bl[buf][g][1]);
                mma_bf16(acc[mi][2 * g + 1], ah[buf][mi], bl[buf][g][2], bl[buf][g][3]);
            }
    };

    constexpr int NK = KDIM / 64;   // 12 or 48 (>= 3)
    load_stage(0, 0);
    load_stage(1, 64);
    load_stage(2, 128);

    for (int it = 0; it < NK; it++) {
        int s = it % 3;
        asm volatile("cp.async.wait_group 2;" ::: "memory");
        __syncthreads();
        // refill the slot consumed at it-1 (== (it+2)%3) for iteration it+2
        if (it + 3 <= NK - 1 + 1 && it + 3 - 1 < NK) {}
        if (it + 3 <= NK) { /* placeholder */ }
        if (it >= 1 && it + 2 < NK) load_stage((it + 2) % 3, (it + 2) * 64);
        uint32_t sA = sb0 + s * STG_B;
        uint32_t sB = sA + B_BASE;
        ldfrags(0, 0, sA, sB);
        #pragma unroll
        for (int k16 = 0; k16 < 4; k16++) {
            if (k16 < 3) ldfrags((k16 + 1) & 1, k16 + 1, sA, sB);
            do_mma(k16 & 1);
        }
    }
    asm volatile("cp.async.wait_group 0;" ::: "memory");
    __syncthreads();

    // ---- epilogue via smem staging, pitch 132 floats ----
    float* epi = (float*)smem;
    const float* bvec = bias + (size_t)e * NTOT + n0;
    int g4 = lane >> 2, t4 = lane & 3;
    #pragma unroll
    for (int mi = 0; mi < 2; mi++) {
        int r0 = WM + mi * 16 + g4;
        float gate0 = 0.f, gate8 = 0.f;
        if (EPI == 2) {
            if (m0 + r0 < cnt)     gate0 = g_gates[e * T_TOK + m0 + r0];
            if (m0 + r0 + 8 < cnt) gate8 = g_gates[e * T_TOK + m0 + r0 + 8];
        }
        #pragma unroll
        for (int ni = 0; ni < 8; ni++) {
            int col = WN + ni * 8 + t4 * 2;
            float b0 = bvec[col], b1 = bvec[col + 1];
            float* a = acc[mi][ni];
            if (EPI == 1) {
                epi[r0 * 132 + col]           = fmaxf(a[0] + b0, 0.f);
                epi[r0 * 132 + col + 1]       = fmaxf(a[1] + b1, 0.f);
                epi[(r0 + 8) * 132 + col]     = fmaxf(a[2] + b0, 0.f);
                epi[(r0 + 8) * 132 + col + 1] = fmaxf(a[3] + b1, 0.f);
            } else {
                epi[r0 * 132 + col]           = (a[0] + b0) * gate0;
                epi[r0 * 132 + col + 1]       = (a[1] + b1) * gate0;
                epi[(r0 + 8) * 132 + col]     = (a[2] + b0) * gate8;
                epi[(r0 + 8) * 132 + col + 1] = (a[3] + b1) * gate8;
            }
        }
    }
    __syncthreads();

    if (EPI == 1) {
        bf16* Hh = g_Hh + (size_t)(rowbase + m0) * F + n0;
        bf16* Hl = g_Hl + (size_t)(rowbase + m0) * F + n0;
        #pragma unroll
        for (int i = 0; i < 16; i++) {
            int c = tid + i * 256;
            int row = c >> 5, q = c & 31;
            float4 v = *(float4*)&epi[row * 132 + q * 4];
            bf16 h[4], l[4];
            split_bf16(v.x, h[0], l[0]);
            split_bf16(v.y, h[1], l[1]);
            split_bf16(v.z, h[2], l[2]);
            split_bf16(v.w, h[3], l[3]);
            *(uint2*)&Hh[(size_t)row * F + q * 4] = *(uint2*)h;
            *(uint2*)&Hl[(size_t)row * F + q * 4] = *(uint2*)l;
        }
    } else {
        #pragma unroll
        for (int i = 0; i < 16; i++) {
            int c = tid + i * 256;
            int row = c >> 5, q = c & 31;
            if (m0 + row < cnt) {
                int tok = g_list[e * T_TOK + m0 + row];
                float4 v = *(float4*)&epi[row * 132 + q * 4];
                float* op = out + (size_t)tok * D + n0 + q * 4;
                atomicAdd(op + 0, v.x);
                atomicAdd(op + 1, v.y);
                atomicAdd(op + 2, v.z);
                atomicAdd(op + 3, v.w);
            }
        }
    }
}

extern "C" void kernel_launch(void* const* d_in, const int* in_sizes, int n_in,
                              void* d_out, int out_size) {
    const float* x     = (const float*)d_in[0];
    const float* noise = (const float*)d_in[1];
    const float* Wg    = (const float*)d_in[2];
    const float* bg    = (const float*)d_in[3];
    const float* Wn    = (const float*)d_in[4];
    const float* bn    = (const float*)d_in[5];
    const float* W1    = (const float*)d_in[6];
    const float* b1    = (const float*)d_in[7];
    const float* W2    = (const float*)d_in[8];
    const float* b2    = (const float*)d_in[9];
    float* out = (float*)d_out;

    static bool attr_set = false;
    if (!attr_set) {
        cudaFuncSetAttribute(moe_gemm_mma<D, F, 1>, cudaFuncAttributeMaxDynamicSharedMemorySize, SMEM_DYN);
        cudaFuncSetAttribute(moe_gemm_mma<F, D, 2>, cudaFuncAttributeMaxDynamicSharedMemorySize, SMEM_DYN);
        attr_set = true;
    }

    cudaMemsetAsync(out, 0, (size_t)out_size * sizeof(float));
    init_kernel<<<1, 32>>>();
    router_kernel<<<T_TOK, 256>>>(x, noise, Wg, bg, Wn, bn);
    finalize_kernel<<<1, 32>>>();
    gather_split_kernel<<<dim3(E, 256), 256>>>(x);
    split_weights_kernel<<<4096, 256>>>(W1, 0);
    split_weights_kernel<<<4096, 256>>>(W2, 1);
    moe_gemm_mma<D, F, 1><<<dim3(F / 128, T_TOK / 128, E), 256, SMEM_DYN>>>(b1, out);
    moe_gemm_mma<F, D, 2><<<dim3(D / 128, T_TOK / 128, E), 256, SMEM_DYN>>>(b2, out);
}

// round 7
// speedup vs baseline: 5.0944x; 1.3888x over previous
#include <cuda_runtime.h>
#include <cuda_fp16.h>
#include <math.h>
#include <stdint.h>

#define D 768
#define E 8
#define F 3072
#define T_TOK 4096
#define MAXROWS 10240

typedef __half f16;

__device__ int   g_counts[E];
__device__ int   g_off[E + 1];
__device__ int   g_list[E * T_TOK];
__device__ float g_gates[E * T_TOK];
__device__ f16   g_Ah[(size_t)MAXROWS * D];
__device__ f16   g_Al[(size_t)MAXROWS * D];
__device__ f16   g_Hh[(size_t)MAXROWS * F];
__device__ f16   g_Hl[(size_t)MAXROWS * F];
__device__ f16   g_W1[(size_t)E * D * F];   // [E][D][F] native [k][n], fp16
__device__ f16   g_W2[(size_t)E * D * F];   // [E][F][D] native [k][n], fp16

__device__ __forceinline__ uint32_t smem_u32(const void* p) {
    uint32_t a;
    asm("{ .reg .u64 t; cvta.to.shared.u64 t, %1; cvt.u32.u64 %0, t; }" : "=r"(a) : "l"(p));
    return a;
}
__device__ __forceinline__ void cp16(uint32_t dst, const void* src) {
    asm volatile("cp.async.cg.shared.global [%0], [%1], 16;"
                 :: "r"(dst), "l"(__cvta_generic_to_global(src)));
}
#define CP_COMMIT() asm volatile("cp.async.commit_group;" ::: "memory")

__device__ __forceinline__ void ldm_x4(uint32_t* r, uint32_t addr) {
    asm volatile("ldmatrix.sync.aligned.m8n8.x4.shared.b16 {%0,%1,%2,%3}, [%4];"
                 : "=r"(r[0]), "=r"(r[1]), "=r"(r[2]), "=r"(r[3]) : "r"(addr));
}
__device__ __forceinline__ void ldm_x4_t(uint32_t* r, uint32_t addr) {
    asm volatile("ldmatrix.sync.aligned.m8n8.x4.trans.shared.b16 {%0,%1,%2,%3}, [%4];"
                 : "=r"(r[0]), "=r"(r[1]), "=r"(r[2]), "=r"(r[3]) : "r"(addr));
}
__device__ __forceinline__ void mma_f16(float* c, const uint32_t* a, uint32_t b0, uint32_t b1) {
    asm volatile("mma.sync.aligned.m16n8k16.row.col.f32.f16.f16.f32 "
                 "{%0,%1,%2,%3}, {%4,%5,%6,%7}, {%8,%9}, {%0,%1,%2,%3};"
                 : "+f"(c[0]), "+f"(c[1]), "+f"(c[2]), "+f"(c[3])
                 : "r"(a[0]), "r"(a[1]), "r"(a[2]), "r"(a[3]), "r"(b0), "r"(b1));
}
__device__ __forceinline__ void split_h(float v, f16& hi, f16& lo) {
    hi = __float2half_rn(v);
    lo = __float2half_rn(v - __half2float(hi));
}

__global__ void init_kernel() { if (threadIdx.x < E) g_counts[threadIdx.x] = 0; }

__global__ void router_kernel(const float* __restrict__ x, const float* __restrict__ noise,
                              const float* __restrict__ Wg, const float* __restrict__ bg,
                              const float* __restrict__ Wn, const float* __restrict__ bn) {
    int t = blockIdx.x, tid = threadIdx.x, w = tid >> 5, lane = tid & 31;
    __shared__ float xs[D];
    __shared__ float noisy[E];
    const float* xr = x + (size_t)t * D;
    for (int i = tid; i < D; i += 256) xs[i] = xr[i];
    __syncthreads();
    float sg = 0.f, sn = 0.f;
    for (int i = lane; i < D; i += 32) {
        float xv = xs[i];
        sg += xv * Wg[i * E + w];
        sn += xv * Wn[i * E + w];
    }
    #pragma unroll
    for (int o = 16; o > 0; o >>= 1) {
        sg += __shfl_down_sync(~0u, sg, o);
        sn += __shfl_down_sync(~0u, sn, o);
    }
    if (lane == 0) {
        float lg = sg + bg[w], ln = sn + bn[w];
        float sp = (ln > 20.f) ? ln : log1pf(expf(ln));
        noisy[w] = lg + noise[(size_t)t * E + w] * sp;
    }
    __syncthreads();
    if (tid == 0) {
        int i1 = 0; float v1 = noisy[0];
        #pragma unroll
        for (int e = 1; e < E; e++) if (noisy[e] > v1) { v1 = noisy[e]; i1 = e; }
        int i2 = -1; float v2 = -3.4e38f;
        #pragma unroll
        for (int e = 0; e < E; e++) {
            if (e == i1) continue;
            if (noisy[e] > v2) { v2 = noisy[e]; i2 = e; }
        }
        float eb = expf(v2 - v1);
        float p1 = 1.f / (1.f + eb), p2 = eb / (1.f + eb);
        if (p1 > 1e-9f) {
            int pos = atomicAdd(&g_counts[i1], 1);
            g_list[i1 * T_TOK + pos] = t; g_gates[i1 * T_TOK + pos] = p1;
        }
        if (p2 > 1e-9f) {
            int pos = atomicAdd(&g_counts[i2], 1);
            g_list[i2 * T_TOK + pos] = t; g_gates[i2 * T_TOK + pos] = p2;
        }
    }
}

__global__ void finalize_kernel() {
    if (threadIdx.x == 0) {
        int off = 0;
        for (int e = 0; e < E; e++) { g_off[e] = off; off += (g_counts[e] + 127) & ~127; }
        g_off[E] = off;
    }
}

__global__ void __launch_bounds__(256) gather_split_kernel(const float* __restrict__ x) {
    int e = blockIdx.x;
    int cnt = g_counts[e], pad = (cnt + 127) & ~127;
    int rb = blockIdx.y * 16;
    if (rb >= pad) return;
    int base = g_off[e];
    const int Q = D / 4;
    for (int idx = threadIdx.x; idx < 16 * Q; idx += 256) {
        int m = rb + idx / Q, q = idx % Q;
        float4 v = make_float4(0.f, 0.f, 0.f, 0.f);
        if (m < cnt)
            v = *(const float4*)&x[(size_t)g_list[e * T_TOK + m] * D + q * 4];
        f16 h[4], l[4];
        split_h(v.x, h[0], l[0]);
        split_h(v.y, h[1], l[1]);
        split_h(v.z, h[2], l[2]);
        split_h(v.w, h[3], l[3]);
        size_t o = (size_t)(base + m) * D + q * 4;
        *(uint2*)&g_Ah[o] = *(uint2*)h;
        *(uint2*)&g_Al[o] = *(uint2*)l;
    }
}

// single fp16 conversion of weights (no lo term needed)
__global__ void __launch_bounds__(256) split_weights_kernel(const float* __restrict__ W, int which) {
    f16* Th = which ? g_W2 : g_W1;
    const size_t n4 = (size_t)E * D * F / 4;
    size_t stride = (size_t)gridDim.x * blockDim.x;
    for (size_t i = (size_t)blockIdx.x * blockDim.x + threadIdx.x; i < n4; i += stride) {
        float4 v = *(const float4*)&W[i * 4];
        f16 h[4];
        h[0] = __float2half_rn(v.x);
        h[1] = __float2half_rn(v.y);
        h[2] = __float2half_rn(v.z);
        h[3] = __float2half_rn(v.w);
        *(uint2*)&Th[i * 4] = *(uint2*)h;
    }
}

// ------------- mma.sync fp16 2-term split GEMM -------------
// CTA 128 x CTA_N, K-step 64, 3 smem stages, 8 warps.
// CTA_N=256: warp 64x64 (2Mw x 4Nw). CTA_N=128: warp 32x64 (4Mw x 2Nw).
#define A_PITCH 144
#define A_ARR   18432

template<int KDIM, int NTOT, int CTA_N, int EPI>
__global__ void __launch_bounds__(256, 1) moe_gemm_mma(const float* __restrict__ bias,
                                                       float* __restrict__ out) {
    constexpr int B_PITCH = CTA_N * 2 + 16;
    constexpr int B_ARR   = 64 * B_PITCH;
    constexpr int STG     = 2 * A_ARR + B_ARR;
    constexpr int NWN     = CTA_N / 64;            // warps along N
    constexpr int MI      = (128 / (8 / NWN)) / 16; // m16 tiles per warp (4 or 2)
    constexpr int NBS     = (CTA_N == 256) ? 5 : 4; // log2 chunks per B row
    constexpr int NK      = KDIM / 64;

    int e = blockIdx.z, cnt = g_counts[e];
    int m0 = blockIdx.y * 128;
    int pad = (cnt + 127) & ~127;
    if (m0 >= pad) return;
    int n0 = blockIdx.x * CTA_N, rowbase = g_off[e];

    extern __shared__ __align__(1024) char smem[];
    uint32_t sb0 = smem_u32(smem);
    int tid = threadIdx.x, wid = tid >> 5, lane = tid & 31;
    int WM = (wid / NWN) * (MI * 16);
    int WN = (wid % NWN) * 64;

    const f16* Agh = (EPI == 1 ? g_Ah : g_Hh) + (size_t)(rowbase + m0) * KDIM;
    const f16* Agl = (EPI == 1 ? g_Al : g_Hl) + (size_t)(rowbase + m0) * KDIM;
    const f16* Bg  = (EPI == 1 ? g_W1 : g_W2) + (size_t)e * D * F + n0;
    const f16* aptr[2] = {Agh, Agl};

    auto load_stage = [&](int s, int k0) {
        uint32_t sb = sb0 + s * STG;
        constexpr int TOT = 2048 + (64 << NBS);
        #pragma unroll
        for (int i = 0; i < TOT / 256; i++) {
            int c = tid + i * 256;
            if (c < 2048) {
                int arr = c >> 10, rc = c & 1023, row = rc >> 3, ch = rc & 7;
                cp16(sb + arr * A_ARR + row * A_PITCH + ch * 16,
                     aptr[arr] + (size_t)row * KDIM + k0 + ch * 8);
            } else {
                int cb = c - 2048, row = cb >> NBS, ch = cb & ((1 << NBS) - 1);
                cp16(sb + 2 * A_ARR + row * B_PITCH + ch * 16,
                     Bg + (size_t)(k0 + row) * NTOT + ch * 8);
            }
        }
        CP_COMMIT();
    };

    float acc[MI][8][4];
    #pragma unroll
    for (int mi = 0; mi < MI; mi++)
        #pragma unroll
        for (int ni = 0; ni < 8; ni++)
            #pragma unroll
            for (int q = 0; q < 4; q++) acc[mi][ni][q] = 0.f;

    uint32_t a_off = (uint32_t)((lane & 15) * A_PITCH + (lane >> 4) * 16);
    uint32_t b_off = (uint32_t)((lane & 15) * B_PITCH + (lane >> 4) * 16);

    load_stage(0, 0);
    load_stage(1, 64);

    for (int it = 0; it < NK; it++) {
        int s = it % 3;
        if (it + 1 < NK) asm volatile("cp.async.wait_group 1;" ::: "memory");
        else             asm volatile("cp.async.wait_group 0;" ::: "memory");
        __syncthreads();
        if (it + 2 < NK) load_stage((it + 2) % 3, (it + 2) * 64);

        uint32_t sA = sb0 + s * STG;
        uint32_t sB = sA + 2 * A_ARR;
        #pragma unroll
        for (int k16 = 0; k16 < 4; k16++) {
            uint32_t ah[MI][4], al[MI][4], bh[4][4];
            #pragma unroll
            for (int mi = 0; mi < MI; mi++) {
                uint32_t base = sA + (WM + mi * 16) * A_PITCH + k16 * 32 + a_off;
                ldm_x4(ah[mi], base);
                ldm_x4(al[mi], base + A_ARR);
            }
            #pragma unroll
            for (int g = 0; g < 4; g++) {
                uint32_t base = sB + k16 * 16 * B_PITCH + (WN + g * 16) * 2 + b_off;
                ldm_x4_t(bh[g], base);
            }
            #pragma unroll
            for (int mi = 0; mi < MI; mi++)
                #pragma unroll
                for (int g = 0; g < 4; g++) {
                    mma_f16(acc[mi][2 * g],     ah[mi], bh[g][0], bh[g][1]);
                    mma_f16(acc[mi][2 * g + 1], ah[mi], bh[g][2], bh[g][3]);
                }
            #pragma unroll
            for (int mi = 0; mi < MI; mi++)
                #pragma unroll
                for (int g = 0; g < 4; g++) {
                    mma_f16(acc[mi][2 * g],     al[mi], bh[g][0], bh[g][1]);
                    mma_f16(acc[mi][2 * g + 1], al[mi], bh[g][2], bh[g][3]);
                }
        }
    }
    __syncthreads();

    // ---- epilogue via smem staging ----
    constexpr int EPITCH = CTA_N + 4;
    float* epi = (float*)smem;
    const float* bvec = bias + (size_t)e * NTOT + n0;
    int g4 = lane >> 2, t4 = lane & 3;
    #pragma unroll
    for (int mi = 0; mi < MI; mi++) {
        int r0 = WM + mi * 16 + g4;
        float gate0 = 0.f, gate8 = 0.f;
        if (EPI == 2) {
            if (m0 + r0 < cnt)     gate0 = g_gates[e * T_TOK + m0 + r0];
            if (m0 + r0 + 8 < cnt) gate8 = g_gates[e * T_TOK + m0 + r0 + 8];
        }
        #pragma unroll
        for (int ni = 0; ni < 8; ni++) {
            int col = WN + ni * 8 + t4 * 2;
            float b0 = bvec[col], b1 = bvec[col + 1];
            float* a = acc[mi][ni];
            if (EPI == 1) {
                epi[r0 * EPITCH + col]           = fmaxf(a[0] + b0, 0.f);
                epi[r0 * EPITCH + col + 1]       = fmaxf(a[1] + b1, 0.f);
                epi[(r0 + 8) * EPITCH + col]     = fmaxf(a[2] + b0, 0.f);
                epi[(r0 + 8) * EPITCH + col + 1] = fmaxf(a[3] + b1, 0.f);
            } else {
                epi[r0 * EPITCH + col]           = (a[0] + b0) * gate0;
                epi[r0 * EPITCH + col + 1]       = (a[1] + b1) * gate0;
                epi[(r0 + 8) * EPITCH + col]     = (a[2] + b0) * gate8;
                epi[(r0 + 8) * EPITCH + col + 1] = (a[3] + b1) * gate8;
            }
        }
    }
    __syncthreads();

    constexpr int QS = (CTA_N == 256) ? 6 : 5;       // float4 per row log2
    constexpr int WITERS = 128 * (CTA_N / 4) / 256;
    if (EPI == 1) {
        f16* Hh = g_Hh + (size_t)(rowbase + m0) * F + n0;
        f16* Hl = g_Hl + (size_t)(rowbase + m0) * F + n0;
        #pragma unroll
        for (int i = 0; i < WITERS; i++) {
            int c = tid + i * 256;
            int row = c >> QS, q = c & ((1 << QS) - 1);
            float4 v = *(float4*)&epi[row * EPITCH + q * 4];
            f16 h[4], l[4];
            split_h(v.x, h[0], l[0]);
            split_h(v.y, h[1], l[1]);
            split_h(v.z, h[2], l[2]);
            split_h(v.w, h[3], l[3]);
            *(uint2*)&Hh[(size_t)row * F + q * 4] = *(uint2*)h;
            *(uint2*)&Hl[(size_t)row * F + q * 4] = *(uint2*)l;
        }
    } else {
        #pragma unroll
        for (int i = 0; i < WITERS; i++) {
            int c = tid + i * 256;
            int row = c >> QS, q = c & ((1 << QS) - 1);
            if (m0 + row < cnt) {
                int tok = g_list[e * T_TOK + m0 + row];
                float4 v = *(float4*)&epi[row * EPITCH + q * 4];
                float* op = out + (size_t)tok * D + n0 + q * 4;
                atomicAdd(op + 0, v.x);
                atomicAdd(op + 1, v.y);
                atomicAdd(op + 2, v.z);
                atomicAdd(op + 3, v.w);
            }
        }
    }
}

#define SMEM1 (3 * (2 * A_ARR + 64 * (256 * 2 + 16)))   // 211968
#define SMEM2 (3 * (2 * A_ARR + 64 * (128 * 2 + 16)))   // 162816

extern "C" void kernel_launch(void* const* d_in, const int* in_sizes, int n_in,
                              void* d_out, int out_size) {
    const float* x     = (const float*)d_in[0];
    const float* noise = (const float*)d_in[1];
    const float* Wg    = (const float*)d_in[2];
    const float* bg    = (const float*)d_in[3];
    const float* Wn    = (const float*)d_in[4];
    const float* bn    = (const float*)d_in[5];
    const float* W1    = (const float*)d_in[6];
    const float* b1    = (const float*)d_in[7];
    const float* W2    = (const float*)d_in[8];
    const float* b2    = (const float*)d_in[9];
    float* out = (float*)d_out;

    static bool attr_set = false;
    if (!attr_set) {
        cudaFuncSetAttribute(moe_gemm_mma<D, F, 256, 1>, cudaFuncAttributeMaxDynamicSharedMemorySize, SMEM1);
        cudaFuncSetAttribute(moe_gemm_mma<F, D, 128, 2>, cudaFuncAttributeMaxDynamicSharedMemorySize, SMEM2);
        attr_set = true;
    }

    cudaMemsetAsync(out, 0, (size_t)out_size * sizeof(float));
    init_kernel<<<1, 32>>>();
    router_kernel<<<T_TOK, 256>>>(x, noise, Wg, bg, Wn, bn);
    finalize_kernel<<<1, 32>>>();
    gather_split_kernel<<<dim3(E, 256), 256>>>(x);
    split_weights_kernel<<<4096, 256>>>(W1, 0);
    split_weights_kernel<<<4096, 256>>>(W2, 1);
    moe_gemm_mma<D, F, 256, 1><<<dim3(F / 256, T_TOK / 128, E), 256, SMEM1>>>(b1, out);
    moe_gemm_mma<F, D, 128, 2><<<dim3(D / 128, T_TOK / 128, E), 256, SMEM2>>>(b2, out);
}

// round 8
// speedup vs baseline: 7.5529x; 1.4826x over previous
#include <cuda_runtime.h>
#include <cuda_fp16.h>
#include <math.h>
#include <stdint.h>

#define D 768
#define E 8
#define F 3072
#define T_TOK 4096
#define MAXROWS 10240

typedef __half f16;

__device__ int   g_counts[E];
__device__ int   g_off[E + 1];
__device__ int   g_list[E * T_TOK];
__device__ float g_gates[E * T_TOK];
__device__ f16   g_A[(size_t)MAXROWS * D];
__device__ f16   g_H[(size_t)MAXROWS * F];
__device__ f16   g_W1[(size_t)E * D * F];   // [E][D][F] native [k][n], fp16
__device__ f16   g_W2[(size_t)E * D * F];   // [E][F][D] native [k][n], fp16

__device__ __forceinline__ uint32_t smem_u32(const void* p) {
    uint32_t a;
    asm("{ .reg .u64 t; cvta.to.shared.u64 t, %1; cvt.u32.u64 %0, t; }" : "=r"(a) : "l"(p));
    return a;
}
__device__ __forceinline__ void cp16(uint32_t dst, const void* src) {
    asm volatile("cp.async.cg.shared.global [%0], [%1], 16;"
                 :: "r"(dst), "l"(__cvta_generic_to_global(src)));
}
#define CP_COMMIT() asm volatile("cp.async.commit_group;" ::: "memory")

__device__ __forceinline__ void ldm_x4(uint32_t* r, uint32_t addr) {
    asm volatile("ldmatrix.sync.aligned.m8n8.x4.shared.b16 {%0,%1,%2,%3}, [%4];"
                 : "=r"(r[0]), "=r"(r[1]), "=r"(r[2]), "=r"(r[3]) : "r"(addr));
}
__device__ __forceinline__ void ldm_x4_t(uint32_t* r, uint32_t addr) {
    asm volatile("ldmatrix.sync.aligned.m8n8.x4.trans.shared.b16 {%0,%1,%2,%3}, [%4];"
                 : "=r"(r[0]), "=r"(r[1]), "=r"(r[2]), "=r"(r[3]) : "r"(addr));
}
__device__ __forceinline__ void mma_f16(float* c, const uint32_t* a, uint32_t b0, uint32_t b1) {
    asm volatile("mma.sync.aligned.m16n8k16.row.col.f32.f16.f16.f32 "
                 "{%0,%1,%2,%3}, {%4,%5,%6,%7}, {%8,%9}, {%0,%1,%2,%3};"
                 : "+f"(c[0]), "+f"(c[1]), "+f"(c[2]), "+f"(c[3])
                 : "r"(a[0]), "r"(a[1]), "r"(a[2]), "r"(a[3]), "r"(b0), "r"(b1));
}

__global__ void init_kernel() { if (threadIdx.x < E) g_counts[threadIdx.x] = 0; }

__global__ void router_kernel(const float* __restrict__ x, const float* __restrict__ noise,
                              const float* __restrict__ Wg, const float* __restrict__ bg,
                              const float* __restrict__ Wn, const float* __restrict__ bn) {
    int t = blockIdx.x, tid = threadIdx.x, w = tid >> 5, lane = tid & 31;
    __shared__ float xs[D];
    __shared__ float noisy[E];
    const float* xr = x + (size_t)t * D;
    for (int i = tid; i < D; i += 256) xs[i] = xr[i];
    __syncthreads();
    float sg = 0.f, sn = 0.f;
    for (int i = lane; i < D; i += 32) {
        float xv = xs[i];
        sg += xv * Wg[i * E + w];
        sn += xv * Wn[i * E + w];
    }
    #pragma unroll
    for (int o = 16; o > 0; o >>= 1) {
        sg += __shfl_down_sync(~0u, sg, o);
        sn += __shfl_down_sync(~0u, sn, o);
    }
    if (lane == 0) {
        float lg = sg + bg[w], ln = sn + bn[w];
        float sp = (ln > 20.f) ? ln : log1pf(expf(ln));
        noisy[w] = lg + noise[(size_t)t * E + w] * sp;
    }
    __syncthreads();
    if (tid == 0) {
        int i1 = 0; float v1 = noisy[0];
        #pragma unroll
        for (int e = 1; e < E; e++) if (noisy[e] > v1) { v1 = noisy[e]; i1 = e; }
        int i2 = -1; float v2 = -3.4e38f;
        #pragma unroll
        for (int e = 0; e < E; e++) {
            if (e == i1) continue;
            if (noisy[e] > v2) { v2 = noisy[e]; i2 = e; }
        }
        float eb = expf(v2 - v1);
        float p1 = 1.f / (1.f + eb), p2 = eb / (1.f + eb);
        if (p1 > 1e-9f) {
            int pos = atomicAdd(&g_counts[i1], 1);
            g_list[i1 * T_TOK + pos] = t; g_gates[i1 * T_TOK + pos] = p1;
        }
        if (p2 > 1e-9f) {
            int pos = atomicAdd(&g_counts[i2], 1);
            g_list[i2 * T_TOK + pos] = t; g_gates[i2 * T_TOK + pos] = p2;
        }
    }
}

__global__ void finalize_kernel() {
    if (threadIdx.x == 0) {
        int off = 0;
        for (int e = 0; e < E; e++) { g_off[e] = off; off += (g_counts[e] + 127) & ~127; }
        g_off[E] = off;
    }
}

__global__ void __launch_bounds__(256) gather_kernel(const float* __restrict__ x) {
    int e = blockIdx.x;
    int cnt = g_counts[e], pad = (cnt + 127) & ~127;
    int rb = blockIdx.y * 16;
    if (rb >= pad) return;
    int base = g_off[e];
    const int Q = D / 4;
    for (int idx = threadIdx.x; idx < 16 * Q; idx += 256) {
        int m = rb + idx / Q, q = idx % Q;
        float4 v = make_float4(0.f, 0.f, 0.f, 0.f);
        if (m < cnt)
            v = *(const float4*)&x[(size_t)g_list[e * T_TOK + m] * D + q * 4];
        f16 h[4];
        h[0] = __float2half_rn(v.x);
        h[1] = __float2half_rn(v.y);
        h[2] = __float2half_rn(v.z);
        h[3] = __float2half_rn(v.w);
        *(uint2*)&g_A[(size_t)(base + m) * D + q * 4] = *(uint2*)h;
    }
}

__global__ void __launch_bounds__(256) conv_weights_kernel(const float* __restrict__ W, int which) {
    f16* Th = which ? g_W2 : g_W1;
    const size_t n4 = (size_t)E * D * F / 4;
    size_t stride = (size_t)gridDim.x * blockDim.x;
    for (size_t i = (size_t)blockIdx.x * blockDim.x + threadIdx.x; i < n4; i += stride) {
        float4 v = *(const float4*)&W[i * 4];
        f16 h[4];
        h[0] = __float2half_rn(v.x);
        h[1] = __float2half_rn(v.y);
        h[2] = __float2half_rn(v.z);
        h[3] = __float2half_rn(v.w);
        *(uint2*)&Th[i * 4] = *(uint2*)h;
    }
}

// ------------- pure fp16 mma.sync GEMM -------------
// CTA 128 x CTA_N, K-step 64, 3 smem stages, 8 warps.
// CTA_N=256: warp 64x64 (2Mw x 4Nw). CTA_N=128: warp 32x64 (4Mw x 2Nw).
#define A_PITCH 144
#define A_ARR   18432

template<int KDIM, int NTOT, int CTA_N, int EPI>
__global__ void __launch_bounds__(256, 1) moe_gemm_mma(const float* __restrict__ bias,
                                                       float* __restrict__ out) {
    constexpr int B_PITCH = CTA_N * 2 + 16;
    constexpr int B_ARR   = 64 * B_PITCH;
    constexpr int STG     = A_ARR + B_ARR;
    constexpr int NWN     = CTA_N / 64;
    constexpr int MI      = (128 / (8 / NWN)) / 16;  // 4 (CTA_N=256) or 2 (128)
    constexpr int NBS     = (CTA_N == 256) ? 5 : 4;
    constexpr int NK      = KDIM / 64;

    int e = blockIdx.z, cnt = g_counts[e];
    int m0 = blockIdx.y * 128;
    int pad = (cnt + 127) & ~127;
    if (m0 >= pad) return;
    int n0 = blockIdx.x * CTA_N, rowbase = g_off[e];

    extern __shared__ __align__(1024) char smem[];
    uint32_t sb0 = smem_u32(smem);
    int tid = threadIdx.x, wid = tid >> 5, lane = tid & 31;
    int WM = (wid / NWN) * (MI * 16);
    int WN = (wid % NWN) * 64;

    const f16* Ag = (EPI == 1 ? g_A : g_H) + (size_t)(rowbase + m0) * KDIM;
    const f16* Bg = (EPI == 1 ? g_W1 : g_W2) + (size_t)e * D * F + n0;

    auto load_stage = [&](int s, int k0) {
        uint32_t sb = sb0 + s * STG;
        constexpr int TOT = 1024 + (64 << NBS);
        #pragma unroll
        for (int i = 0; i < TOT / 256; i++) {
            int c = tid + i * 256;
            if (c < 1024) {
                int row = c >> 3, ch = c & 7;
                cp16(sb + row * A_PITCH + ch * 16,
                     Ag + (size_t)row * KDIM + k0 + ch * 8);
            } else {
                int cb = c - 1024, row = cb >> NBS, ch = cb & ((1 << NBS) - 1);
                cp16(sb + A_ARR + row * B_PITCH + ch * 16,
                     Bg + (size_t)(k0 + row) * NTOT + ch * 8);
            }
        }
        CP_COMMIT();
    };

    float acc[MI][8][4];
    #pragma unroll
    for (int mi = 0; mi < MI; mi++)
        #pragma unroll
        for (int ni = 0; ni < 8; ni++)
            #pragma unroll
            for (int q = 0; q < 4; q++) acc[mi][ni][q] = 0.f;

    uint32_t a_off = (uint32_t)((lane & 15) * A_PITCH + (lane >> 4) * 16);
    uint32_t b_off = (uint32_t)((lane & 15) * B_PITCH + (lane >> 4) * 16);

    load_stage(0, 0);
    load_stage(1, 64);

    for (int it = 0; it < NK; it++) {
        int s = it % 3;
        if (it + 1 < NK) asm volatile("cp.async.wait_group 1;" ::: "memory");
        else             asm volatile("cp.async.wait_group 0;" ::: "memory");
        __syncthreads();
        if (it + 2 < NK) load_stage((it + 2) % 3, (it + 2) * 64);

        uint32_t sA = sb0 + s * STG;
        uint32_t sB = sA + A_ARR;
        #pragma unroll
        for (int k16 = 0; k16 < 4; k16++) {
            uint32_t ah[MI][4], bh[4][4];
            #pragma unroll
            for (int mi = 0; mi < MI; mi++)
                ldm_x4(ah[mi], sA + (WM + mi * 16) * A_PITCH + k16 * 32 + a_off);
            #pragma unroll
            for (int g = 0; g < 4; g++)
                ldm_x4_t(bh[g], sB + k16 * 16 * B_PITCH + (WN + g * 16) * 2 + b_off);
            #pragma unroll
            for (int mi = 0; mi < MI; mi++)
                #pragma unroll
                for (int g = 0; g < 4; g++) {
                    mma_f16(acc[mi][2 * g],     ah[mi], bh[g][0], bh[g][1]);
                    mma_f16(acc[mi][2 * g + 1], ah[mi], bh[g][2], bh[g][3]);
                }
        }
    }
    __syncthreads();

    // ---- epilogue via smem staging ----
    constexpr int EPITCH = CTA_N + 4;
    float* epi = (float*)smem;
    const float* bvec = bias + (size_t)e * NTOT + n0;
    int g4 = lane >> 2, t4 = lane & 3;
    #pragma unroll
    for (int mi = 0; mi < MI; mi++) {
        int r0 = WM + mi * 16 + g4;
        float gate0 = 0.f, gate8 = 0.f;
        if (EPI == 2) {
            if (m0 + r0 < cnt)     gate0 = g_gates[e * T_TOK + m0 + r0];
            if (m0 + r0 + 8 < cnt) gate8 = g_gates[e * T_TOK + m0 + r0 + 8];
        }
        #pragma unroll
        for (int ni = 0; ni < 8; ni++) {
            int col = WN + ni * 8 + t4 * 2;
            float b0 = bvec[col], b1 = bvec[col + 1];
            float* a = acc[mi][ni];
            if (EPI == 1) {
                epi[r0 * EPITCH + col]           = fmaxf(a[0] + b0, 0.f);
                epi[r0 * EPITCH + col + 1]       = fmaxf(a[1] + b1, 0.f);
                epi[(r0 + 8) * EPITCH + col]     = fmaxf(a[2] + b0, 0.f);
                epi[(r0 + 8) * EPITCH + col + 1] = fmaxf(a[3] + b1, 0.f);
            } else {
                epi[r0 * EPITCH + col]           = (a[0] + b0) * gate0;
                epi[r0 * EPITCH + col + 1]       = (a[1] + b1) * gate0;
                epi[(r0 + 8) * EPITCH + col]     = (a[2] + b0) * gate8;
                epi[(r0 + 8) * EPITCH + col + 1] = (a[3] + b1) * gate8;
            }
        }
    }
    __syncthreads();

    constexpr int QS = (CTA_N == 256) ? 6 : 5;
    constexpr int WITERS = 128 * (CTA_N / 4) / 256;
    if (EPI == 1) {
        f16* Hp = g_H + (size_t)(rowbase + m0) * F + n0;
        #pragma unroll
        for (int i = 0; i < WITERS; i++) {
            int c = tid + i * 256;
            int row = c >> QS, q = c & ((1 << QS) - 1);
            float4 v = *(float4*)&epi[row * EPITCH + q * 4];
            f16 h[4];
            h[0] = __float2half_rn(v.x);
            h[1] = __float2half_rn(v.y);
            h[2] = __float2half_rn(v.z);
            h[3] = __float2half_rn(v.w);
            *(uint2*)&Hp[(size_t)row * F + q * 4] = *(uint2*)h;
        }
    } else {
        #pragma unroll
        for (int i = 0; i < WITERS; i++) {
            int c = tid + i * 256;
            int row = c >> QS, q = c & ((1 << QS) - 1);
            if (m0 + row < cnt) {
                int tok = g_list[e * T_TOK + m0 + row];
                float4 v = *(float4*)&epi[row * EPITCH + q * 4];
                float* op = out + (size_t)tok * D + n0 + q * 4;
                atomicAdd(op + 0, v.x);
                atomicAdd(op + 1, v.y);
                atomicAdd(op + 2, v.z);
                atomicAdd(op + 3, v.w);
            }
        }
    }
}

#define SMEM1 (3 * (A_ARR + 64 * (256 * 2 + 16)))   // 156672
#define SMEM2 (3 * (A_ARR + 64 * (128 * 2 + 16)))   // 107520

extern "C" void kernel_launch(void* const* d_in, const int* in_sizes, int n_in,
                              void* d_out, int out_size) {
    const float* x     = (const float*)d_in[0];
    const float* noise = (const float*)d_in[1];
    const float* Wg    = (const float*)d_in[2];
    const float* bg    = (const float*)d_in[3];
    const float* Wn    = (const float*)d_in[4];
    const float* bn    = (const float*)d_in[5];
    const float* W1    = (const float*)d_in[6];
    const float* b1    = (const float*)d_in[7];
    const float* W2    = (const float*)d_in[8];
    const float* b2    = (const float*)d_in[9];
    float* out = (float*)d_out;

    static bool attr_set = false;
    if (!attr_set) {
        cudaFuncSetAttribute(moe_gemm_mma<D, F, 256, 1>, cudaFuncAttributeMaxDynamicSharedMemorySize, SMEM1);
        cudaFuncSetAttribute(moe_gemm_mma<F, D, 128, 2>, cudaFuncAttributeMaxDynamicSharedMemorySize, SMEM2);
        attr_set = true;
    }

    cudaMemsetAsync(out, 0, (size_t)out_size * sizeof(float));
    init_kernel<<<1, 32>>>();
    router_kernel<<<T_TOK, 256>>>(x, noise, Wg, bg, Wn, bn);
    finalize_kernel<<<1, 32>>>();
    gather_kernel<<<dim3(E, 256), 256>>>(x);
    conv_weights_kernel<<<4096, 256>>>(W1, 0);
    conv_weights_kernel<<<4096, 256>>>(W2, 1);
    moe_gemm_mma<D, F, 256, 1><<<dim3(F / 256, T_TOK / 128, E), 256, SMEM1>>>(b1, out);
    moe_gemm_mma<F, D, 128, 2><<<dim3(D / 128, T_TOK / 128, E), 256, SMEM2>>>(b2, out);
}

// round 9
// speedup vs baseline: 8.6263x; 1.1421x over previous
#include <cuda_runtime.h>
#include <cuda_fp16.h>
#include <math.h>
#include <stdint.h>

#define D 768
#define E 8
#define F 3072
#define T_TOK 4096
#define MAXROWS 10240

typedef __half f16;

__device__ int   g_counts[E];
__device__ int   g_off[E + 1];
__device__ int   g_list[E * T_TOK];
__device__ float g_gates[E * T_TOK];
__device__ f16   g_A[(size_t)MAXROWS * D];
__device__ f16   g_H[(size_t)MAXROWS * F];
__device__ f16   g_W1[(size_t)E * D * F];   // [E][D][F] native [k][n], fp16
__device__ f16   g_W2[(size_t)E * D * F];   // [E][F][D] native [k][n], fp16

__device__ __forceinline__ uint32_t smem_u32(const void* p) {
    uint32_t a;
    asm("{ .reg .u64 t; cvta.to.shared.u64 t, %1; cvt.u32.u64 %0, t; }" : "=r"(a) : "l"(p));
    return a;
}
__device__ __forceinline__ void cp16(uint32_t dst, const void* src) {
    asm volatile("cp.async.cg.shared.global [%0], [%1], 16;"
                 :: "r"(dst), "l"(__cvta_generic_to_global(src)));
}
#define CP_COMMIT() asm volatile("cp.async.commit_group;" ::: "memory")

__device__ __forceinline__ void ldm_x4(uint32_t* r, uint32_t addr) {
    asm volatile("ldmatrix.sync.aligned.m8n8.x4.shared.b16 {%0,%1,%2,%3}, [%4];"
                 : "=r"(r[0]), "=r"(r[1]), "=r"(r[2]), "=r"(r[3]) : "r"(addr));
}
__device__ __forceinline__ void ldm_x4_t(uint32_t* r, uint32_t addr) {
    asm volatile("ldmatrix.sync.aligned.m8n8.x4.trans.shared.b16 {%0,%1,%2,%3}, [%4];"
                 : "=r"(r[0]), "=r"(r[1]), "=r"(r[2]), "=r"(r[3]) : "r"(addr));
}
__device__ __forceinline__ void mma_f16(float* c, const uint32_t* a, uint32_t b0, uint32_t b1) {
    asm volatile("mma.sync.aligned.m16n8k16.row.col.f32.f16.f16.f32 "
                 "{%0,%1,%2,%3}, {%4,%5,%6,%7}, {%8,%9}, {%0,%1,%2,%3};"
                 : "+f"(c[0]), "+f"(c[1]), "+f"(c[2]), "+f"(c[3])
                 : "r"(a[0]), "r"(a[1]), "r"(a[2]), "r"(a[3]), "r"(b0), "r"(b1));
}

__global__ void init_kernel() { if (threadIdx.x < E) g_counts[threadIdx.x] = 0; }

__global__ void router_kernel(const float* __restrict__ x, const float* __restrict__ noise,
                              const float* __restrict__ Wg, const float* __restrict__ bg,
                              const float* __restrict__ Wn, const float* __restrict__ bn) {
    int t = blockIdx.x, tid = threadIdx.x, w = tid >> 5, lane = tid & 31;
    __shared__ float xs[D];
    __shared__ float noisy[E];
    const float* xr = x + (size_t)t * D;
    for (int i = tid; i < D; i += 256) xs[i] = xr[i];
    __syncthreads();
    float sg = 0.f, sn = 0.f;
    for (int i = lane; i < D; i += 32) {
        float xv = xs[i];
        sg += xv * Wg[i * E + w];
        sn += xv * Wn[i * E + w];
    }
    #pragma unroll
    for (int o = 16; o > 0; o >>= 1) {
        sg += __shfl_down_sync(~0u, sg, o);
        sn += __shfl_down_sync(~0u, sn, o);
    }
    if (lane == 0) {
        float lg = sg + bg[w], ln = sn + bn[w];
        float sp = (ln > 20.f) ? ln : log1pf(expf(ln));
        noisy[w] = lg + noise[(size_t)t * E + w] * sp;
    }
    __syncthreads();
    if (tid == 0) {
        int i1 = 0; float v1 = noisy[0];
        #pragma unroll
        for (int e = 1; e < E; e++) if (noisy[e] > v1) { v1 = noisy[e]; i1 = e; }
        int i2 = -1; float v2 = -3.4e38f;
        #pragma unroll
        for (int e = 0; e < E; e++) {
            if (e == i1) continue;
            if (noisy[e] > v2) { v2 = noisy[e]; i2 = e; }
        }
        float eb = expf(v2 - v1);
        float p1 = 1.f / (1.f + eb), p2 = eb / (1.f + eb);
        if (p1 > 1e-9f) {
            int pos = atomicAdd(&g_counts[i1], 1);
            g_list[i1 * T_TOK + pos] = t; g_gates[i1 * T_TOK + pos] = p1;
        }
        if (p2 > 1e-9f) {
            int pos = atomicAdd(&g_counts[i2], 1);
            g_list[i2 * T_TOK + pos] = t; g_gates[i2 * T_TOK + pos] = p2;
        }
    }
}

__global__ void finalize_kernel() {
    if (threadIdx.x == 0) {
        int off = 0;
        for (int e = 0; e < E; e++) { g_off[e] = off; off += (g_counts[e] + 127) & ~127; }
        g_off[E] = off;
    }
}

__global__ void __launch_bounds__(256) gather_kernel(const float* __restrict__ x) {
    int e = blockIdx.x;
    int cnt = g_counts[e], pad = (cnt + 127) & ~127;
    int rb = blockIdx.y * 16;
    if (rb >= pad) return;
    int base = g_off[e];
    const int Q = D / 4;
    for (int idx = threadIdx.x; idx < 16 * Q; idx += 256) {
        int m = rb + idx / Q, q = idx % Q;
        float4 v = make_float4(0.f, 0.f, 0.f, 0.f);
        if (m < cnt)
            v = *(const float4*)&x[(size_t)g_list[e * T_TOK + m] * D + q * 4];
        f16 h[4];
        h[0] = __float2half_rn(v.x);
        h[1] = __float2half_rn(v.y);
        h[2] = __float2half_rn(v.z);
        h[3] = __float2half_rn(v.w);
        *(uint2*)&g_A[(size_t)(base + m) * D + q * 4] = *(uint2*)h;
    }
}

__global__ void __launch_bounds__(256) conv_weights_kernel(const float* __restrict__ W, int which) {
    f16* Th = which ? g_W2 : g_W1;
    const size_t n4 = (size_t)E * D * F / 4;
    size_t stride = (size_t)gridDim.x * blockDim.x;
    for (size_t i = (size_t)blockIdx.x * blockDim.x + threadIdx.x; i < n4; i += stride) {
        float4 v = *(const float4*)&W[i * 4];
        f16 h[4];
        h[0] = __float2half_rn(v.x);
        h[1] = __float2half_rn(v.y);
        h[2] = __float2half_rn(v.z);
        h[3] = __float2half_rn(v.w);
        *(uint2*)&Th[i * 4] = *(uint2*)h;
    }
}

// ------------- pure fp16 mma.sync GEMM -------------
// CTA 128 x 128, K-step 64, 3 smem stages, 8 warps (4M x 2N, warp 32x64), 2 CTAs/SM.
#define A_PITCH 144
#define A_ARR   18432
#define B_PITCH 272
#define B_ARR   17408
#define STG     35840
#define SMEM_G  107520    // 3 stages

template<int KDIM, int NTOT, int EPI>
__global__ void __launch_bounds__(256, 2) moe_gemm_mma(const float* __restrict__ bias,
                                                       float* __restrict__ out) {
    constexpr int NK = KDIM / 64;

    int e = blockIdx.z, cnt = g_counts[e];
    int m0 = blockIdx.y * 128;
    int pad = (cnt + 127) & ~127;
    if (m0 >= pad) return;
    int n0 = blockIdx.x * 128, rowbase = g_off[e];

    extern __shared__ __align__(1024) char smem[];
    uint32_t sb0 = smem_u32(smem);
    int tid = threadIdx.x, wid = tid >> 5, lane = tid & 31;
    int WM = (wid >> 1) * 32;
    int WN = (wid & 1) * 64;

    const f16* Ag = (EPI == 1 ? g_A : g_H) + (size_t)(rowbase + m0) * KDIM;
    const f16* Bg = (EPI == 1 ? g_W1 : g_W2) + (size_t)e * D * F + n0;

    auto load_stage = [&](int s, int k0) {
        uint32_t sb = sb0 + s * STG;
        #pragma unroll
        for (int i = 0; i < 8; i++) {
            int c = tid + i * 256;
            if (c < 1024) {            // A: 128 rows x 8 chunks of 16B
                int row = c >> 3, ch = c & 7;
                cp16(sb + row * A_PITCH + ch * 16,
                     Ag + (size_t)row * KDIM + k0 + ch * 8);
            } else {                   // B: 64 k-rows x 16 chunks of 16B
                int cb = c - 1024, row = cb >> 4, ch = cb & 15;
                cp16(sb + A_ARR + row * B_PITCH + ch * 16,
                     Bg + (size_t)(k0 + row) * NTOT + ch * 8);
            }
        }
        CP_COMMIT();
    };

    float acc[2][8][4];
    #pragma unroll
    for (int mi = 0; mi < 2; mi++)
        #pragma unroll
        for (int ni = 0; ni < 8; ni++)
            #pragma unroll
            for (int q = 0; q < 4; q++) acc[mi][ni][q] = 0.f;

    uint32_t a_off = (uint32_t)((lane & 15) * A_PITCH + (lane >> 4) * 16);
    uint32_t b_off = (uint32_t)((lane & 15) * B_PITCH + (lane >> 4) * 16);

    load_stage(0, 0);
    load_stage(1, 64);

    for (int it = 0; it < NK; it++) {
        int s = it % 3;
        if (it + 1 < NK) asm volatile("cp.async.wait_group 1;" ::: "memory");
        else             asm volatile("cp.async.wait_group 0;" ::: "memory");
        __syncthreads();
        if (it + 2 < NK) load_stage((it + 2) % 3, (it + 2) * 64);

        uint32_t sA = sb0 + s * STG;
        uint32_t sB = sA + A_ARR;
        #pragma unroll
        for (int k16 = 0; k16 < 4; k16++) {
            uint32_t ah[2][4], bh[4][4];
            #pragma unroll
            for (int mi = 0; mi < 2; mi++)
                ldm_x4(ah[mi], sA + (WM + mi * 16) * A_PITCH + k16 * 32 + a_off);
            #pragma unroll
            for (int g = 0; g < 4; g++)
                ldm_x4_t(bh[g], sB + k16 * 16 * B_PITCH + (WN + g * 16) * 2 + b_off);
            #pragma unroll
            for (int mi = 0; mi < 2; mi++)
                #pragma unroll
                for (int g = 0; g < 4; g++) {
                    mma_f16(acc[mi][2 * g],     ah[mi], bh[g][0], bh[g][1]);
                    mma_f16(acc[mi][2 * g + 1], ah[mi], bh[g][2], bh[g][3]);
                }
        }
    }
    __syncthreads();

    // ---- epilogue via smem staging (pitch 132 floats, 67.6 KB <= 107.5 KB) ----
    constexpr int EPITCH = 132;
    float* epi = (float*)smem;
    const float* bvec = bias + (size_t)e * NTOT + n0;
    int g4 = lane >> 2, t4 = lane & 3;
    #pragma unroll
    for (int mi = 0; mi < 2; mi++) {
        int r0 = WM + mi * 16 + g4;
        float gate0 = 0.f, gate8 = 0.f;
        if (EPI == 2) {
            if (m0 + r0 < cnt)     gate0 = g_gates[e * T_TOK + m0 + r0];
            if (m0 + r0 + 8 < cnt) gate8 = g_gates[e * T_TOK + m0 + r0 + 8];
        }
        #pragma unroll
        for (int ni = 0; ni < 8; ni++) {
            int col = WN + ni * 8 + t4 * 2;
            float b0 = bvec[col], b1 = bvec[col + 1];
            float* a = acc[mi][ni];
            if (EPI == 1) {
                epi[r0 * EPITCH + col]           = fmaxf(a[0] + b0, 0.f);
                epi[r0 * EPITCH + col + 1]       = fmaxf(a[1] + b1, 0.f);
                epi[(r0 + 8) * EPITCH + col]     = fmaxf(a[2] + b0, 0.f);
                epi[(r0 + 8) * EPITCH + col + 1] = fmaxf(a[3] + b1, 0.f);
            } else {
                epi[r0 * EPITCH + col]           = (a[0] + b0) * gate0;
                epi[r0 * EPITCH + col + 1]       = (a[1] + b1) * gate0;
                epi[(r0 + 8) * EPITCH + col]     = (a[2] + b0) * gate8;
                epi[(r0 + 8) * EPITCH + col + 1] = (a[3] + b1) * gate8;
            }
        }
    }
    __syncthreads();

    if (EPI == 1) {
        f16* Hp = g_H + (size_t)(rowbase + m0) * F + n0;
        #pragma unroll
        for (int i = 0; i < 16; i++) {
            int c = tid + i * 256;
            int row = c >> 5, q = c & 31;
            float4 v = *(float4*)&epi[row * EPITCH + q * 4];
            f16 h[4];
            h[0] = __float2half_rn(v.x);
            h[1] = __float2half_rn(v.y);
            h[2] = __float2half_rn(v.z);
            h[3] = __float2half_rn(v.w);
            *(uint2*)&Hp[(size_t)row * F + q * 4] = *(uint2*)h;
        }
    } else {
        #pragma unroll
        for (int i = 0; i < 16; i++) {
            int c = tid + i * 256;
            int row = c >> 5, q = c & 31;
            if (m0 + row < cnt) {
                int tok = g_list[e * T_TOK + m0 + row];
                float4 v = *(float4*)&epi[row * EPITCH + q * 4];
                float* op = out + (size_t)tok * D + n0 + q * 4;
                atomicAdd(op + 0, v.x);
                atomicAdd(op + 1, v.y);
                atomicAdd(op + 2, v.z);
                atomicAdd(op + 3, v.w);
            }
        }
    }
}

extern "C" void kernel_launch(void* const* d_in, const int* in_sizes, int n_in,
                              void* d_out, int out_size) {
    const float* x     = (const float*)d_in[0];
    const float* noise = (const float*)d_in[1];
    const float* Wg    = (const float*)d_in[2];
    const float* bg    = (const float*)d_in[3];
    const float* Wn    = (const float*)d_in[4];
    const float* bn    = (const float*)d_in[5];
    const float* W1    = (const float*)d_in[6];
    const float* b1    = (const float*)d_in[7];
    const float* W2    = (const float*)d_in[8];
    const float* b2    = (const float*)d_in[9];
    float* out = (float*)d_out;

    static bool attr_set = false;
    if (!attr_set) {
        cudaFuncSetAttribute(moe_gemm_mma<D, F, 1>, cudaFuncAttributeMaxDynamicSharedMemorySize, SMEM_G);
        cudaFuncSetAttribute(moe_gemm_mma<F, D, 2>, cudaFuncAttributeMaxDynamicSharedMemorySize, SMEM_G);
        attr_set = true;
    }

    cudaMemsetAsync(out, 0, (size_t)out_size * sizeof(float));
    init_kernel<<<1, 32>>>();
    router_kernel<<<T_TOK, 256>>>(x, noise, Wg, bg, Wn, bn);
    finalize_kernel<<<1, 32>>>();
    gather_kernel<<<dim3(E, 256), 256>>>(x);
    conv_weights_kernel<<<4096, 256>>>(W1, 0);
    conv_weights_kernel<<<4096, 256>>>(W2, 1);
    moe_gemm_mma<D, F, 1><<<dim3(F / 128, T_TOK / 128, E), 256, SMEM_G>>>(b1, out);
    moe_gemm_mma<F, D, 2><<<dim3(D / 128, T_TOK / 128, E), 256, SMEM_G>>>(b2, out);
}

// round 10
// speedup vs baseline: 9.0370x; 1.0476x over previous
#include <cuda_runtime.h>
#include <cuda_fp16.h>
#include <math.h>
#include <stdint.h>

#define D 768
#define E 8
#define F 3072
#define T_TOK 4096
#define MAXROWS 10240

typedef __half f16;

__device__ int   g_counts[E];
__device__ int   g_off[E + 1];
__device__ int   g_list[E * T_TOK];
__device__ float g_gates[E * T_TOK];
__device__ f16   g_A[(size_t)MAXROWS * D];
__device__ f16   g_H[(size_t)MAXROWS * F];
__device__ f16   g_W1[(size_t)E * D * F];   // [E][D][F] native [k][n], fp16
__device__ f16   g_W2[(size_t)E * D * F];   // [E][F][D] native [k][n], fp16

__device__ __forceinline__ uint32_t smem_u32(const void* p) {
    uint32_t a;
    asm("{ .reg .u64 t; cvta.to.shared.u64 t, %1; cvt.u32.u64 %0, t; }" : "=r"(a) : "l"(p));
    return a;
}
__device__ __forceinline__ void cp16(uint32_t dst, const void* src) {
    asm volatile("cp.async.cg.shared.global [%0], [%1], 16;"
                 :: "r"(dst), "l"(__cvta_generic_to_global(src)));
}
#define CP_COMMIT() asm volatile("cp.async.commit_group;" ::: "memory")

__device__ __forceinline__ void ldm_x4(uint32_t* r, uint32_t addr) {
    asm volatile("ldmatrix.sync.aligned.m8n8.x4.shared.b16 {%0,%1,%2,%3}, [%4];"
                 : "=r"(r[0]), "=r"(r[1]), "=r"(r[2]), "=r"(r[3]) : "r"(addr));
}
__device__ __forceinline__ void ldm_x4_t(uint32_t* r, uint32_t addr) {
    asm volatile("ldmatrix.sync.aligned.m8n8.x4.trans.shared.b16 {%0,%1,%2,%3}, [%4];"
                 : "=r"(r[0]), "=r"(r[1]), "=r"(r[2]), "=r"(r[3]) : "r"(addr));
}
__device__ __forceinline__ void mma_f16(float* c, const uint32_t* a, uint32_t b0, uint32_t b1) {
    asm volatile("mma.sync.aligned.m16n8k16.row.col.f32.f16.f16.f32 "
                 "{%0,%1,%2,%3}, {%4,%5,%6,%7}, {%8,%9}, {%0,%1,%2,%3};"
                 : "+f"(c[0]), "+f"(c[1]), "+f"(c[2]), "+f"(c[3])
                 : "r"(a[0]), "r"(a[1]), "r"(a[2]), "r"(a[3]), "r"(b0), "r"(b1));
}

__global__ void init_kernel() { if (threadIdx.x < E) g_counts[threadIdx.x] = 0; }

// warp-per-token router: 8 tokens per 256-thread block, Wg/Wn staged transposed in smem.
#define WPITCH 776
__global__ void __launch_bounds__(256) router_kernel(
        const float* __restrict__ x, const float* __restrict__ noise,
        const float* __restrict__ Wg, const float* __restrict__ bg,
        const float* __restrict__ Wn, const float* __restrict__ bn) {
    __shared__ float wg[E * WPITCH];
    __shared__ float wn[E * WPITCH];
    int tid = threadIdx.x, lane = tid & 31, w = tid >> 5;
    for (int i = tid; i < D * E; i += 256) {
        int d = i >> 3, e = i & 7;
        wg[e * WPITCH + d] = Wg[i];
        wn[e * WPITCH + d] = Wn[i];
    }
    __syncthreads();

    int t = blockIdx.x * 8 + w;
    const float* xr = x + (size_t)t * D;
    float xv[D / 32];
    #pragma unroll
    for (int i = 0; i < D / 32; i++) xv[i] = xr[i * 32 + lane];

    float sg[E], sn[E];
    #pragma unroll
    for (int e = 0; e < E; e++) { sg[e] = 0.f; sn[e] = 0.f; }
    #pragma unroll
    for (int i = 0; i < D / 32; i++) {
        int d = i * 32 + lane;
        #pragma unroll
        for (int e = 0; e < E; e++) {
            sg[e] = fmaf(xv[i], wg[e * WPITCH + d], sg[e]);
            sn[e] = fmaf(xv[i], wn[e * WPITCH + d], sn[e]);
        }
    }
    #pragma unroll
    for (int e = 0; e < E; e++) {
        #pragma unroll
        for (int o = 16; o > 0; o >>= 1) {
            sg[e] += __shfl_xor_sync(~0u, sg[e], o);
            sn[e] += __shfl_xor_sync(~0u, sn[e], o);
        }
    }
    if (lane == 0) {
        float noisy[E];
        #pragma unroll
        for (int e = 0; e < E; e++) {
            float lg = sg[e] + bg[e], ln = sn[e] + bn[e];
            float sp = (ln > 20.f) ? ln : log1pf(expf(ln));
            noisy[e] = lg + noise[(size_t)t * E + e] * sp;
        }
        int i1 = 0; float v1 = noisy[0];
        #pragma unroll
        for (int e = 1; e < E; e++) if (noisy[e] > v1) { v1 = noisy[e]; i1 = e; }
        int i2 = -1; float v2 = -3.4e38f;
        #pragma unroll
        for (int e = 0; e < E; e++) {
            if (e == i1) continue;
            if (noisy[e] > v2) { v2 = noisy[e]; i2 = e; }
        }
        float eb = expf(v2 - v1);
        float p1 = 1.f / (1.f + eb), p2 = eb / (1.f + eb);
        if (p1 > 1e-9f) {
            int pos = atomicAdd(&g_counts[i1], 1);
            g_list[i1 * T_TOK + pos] = t; g_gates[i1 * T_TOK + pos] = p1;
        }
        if (p2 > 1e-9f) {
            int pos = atomicAdd(&g_counts[i2], 1);
            g_list[i2 * T_TOK + pos] = t; g_gates[i2 * T_TOK + pos] = p2;
        }
    }
}

__global__ void finalize_kernel() {
    if (threadIdx.x == 0) {
        int off = 0;
        for (int e = 0; e < E; e++) { g_off[e] = off; off += (g_counts[e] + 127) & ~127; }
        g_off[E] = off;
    }
}

__global__ void __launch_bounds__(256) gather_kernel(const float* __restrict__ x) {
    int e = blockIdx.x;
    int cnt = g_counts[e], pad = (cnt + 127) & ~127;
    int rb = blockIdx.y * 16;
    if (rb >= pad) return;
    int base = g_off[e];
    const int Q = D / 4;
    for (int idx = threadIdx.x; idx < 16 * Q; idx += 256) {
        int m = rb + idx / Q, q = idx % Q;
        float4 v = make_float4(0.f, 0.f, 0.f, 0.f);
        if (m < cnt)
            v = *(const float4*)&x[(size_t)g_list[e * T_TOK + m] * D + q * 4];
        f16 h[4];
        h[0] = __float2half_rn(v.x);
        h[1] = __float2half_rn(v.y);
        h[2] = __float2half_rn(v.z);
        h[3] = __float2half_rn(v.w);
        *(uint2*)&g_A[(size_t)(base + m) * D + q * 4] = *(uint2*)h;
    }
}

__global__ void __launch_bounds__(256) conv_weights_kernel(const float* __restrict__ W, int which) {
    f16* Th = which ? g_W2 : g_W1;
    const size_t n4 = (size_t)E * D * F / 4;
    size_t stride = (size_t)gridDim.x * blockDim.x;
    for (size_t i = (size_t)blockIdx.x * blockDim.x + threadIdx.x; i < n4; i += stride) {
        float4 v = *(const float4*)&W[i * 4];
        f16 h[4];
        h[0] = __float2half_rn(v.x);
        h[1] = __float2half_rn(v.y);
        h[2] = __float2half_rn(v.z);
        h[3] = __float2half_rn(v.w);
        *(uint2*)&Th[i * 4] = *(uint2*)h;
    }
}

// ------------- pure fp16 mma.sync GEMM, optional split-K -------------
// CTA 128 x 128, K-step 64, 3 smem stages, 8 warps (4M x 2N, warp 32x64), 2 CTAs/SM.
#define A_PITCH 144
#define A_ARR   18432
#define B_PITCH 272
#define B_ARR   17408
#define STG     35840
#define SMEM_G  107520    // 3 stages

template<int KTOT, int NTOT, int EPI, int SPLITK>
__global__ void __launch_bounds__(256, 2) moe_gemm_mma(const float* __restrict__ bias,
                                                       float* __restrict__ out) {
    constexpr int KLOC = KTOT / SPLITK;
    constexpr int NK   = KLOC / 64;

    int e = blockIdx.z, cnt = g_counts[e];
    int m0 = blockIdx.y * 128;
    int pad = (cnt + 127) & ~127;
    if (m0 >= pad) return;
    int nt = blockIdx.x / SPLITK;
    int ks = blockIdx.x % SPLITK;
    int n0 = nt * 128, rowbase = g_off[e];
    int kbase = ks * KLOC;

    extern __shared__ __align__(1024) char smem[];
    uint32_t sb0 = smem_u32(smem);
    int tid = threadIdx.x, wid = tid >> 5, lane = tid & 31;
    int WM = (wid >> 1) * 32;
    int WN = (wid & 1) * 64;

    const f16* Ag = (EPI == 1 ? g_A : g_H) + (size_t)(rowbase + m0) * KTOT + kbase;
    const f16* Bg = (EPI == 1 ? g_W1 : g_W2) + (size_t)e * D * F + (size_t)kbase * NTOT + n0;

    auto load_stage = [&](int s, int k0) {
        uint32_t sb = sb0 + s * STG;
        #pragma unroll
        for (int i = 0; i < 8; i++) {
            int c = tid + i * 256;
            if (c < 1024) {            // A: 128 rows x 8 chunks of 16B
                int row = c >> 3, ch = c & 7;
                cp16(sb + row * A_PITCH + ch * 16,
                     Ag + (size_t)row * KTOT + k0 + ch * 8);
            } else {                   // B: 64 k-rows x 16 chunks of 16B
                int cb = c - 1024, row = cb >> 4, ch = cb & 15;
                cp16(sb + A_ARR + row * B_PITCH + ch * 16,
                     Bg + (size_t)(k0 + row) * NTOT + ch * 8);
            }
        }
        CP_COMMIT();
    };

    float acc[2][8][4];
    #pragma unroll
    for (int mi = 0; mi < 2; mi++)
        #pragma unroll
        for (int ni = 0; ni < 8; ni++)
            #pragma unroll
            for (int q = 0; q < 4; q++) acc[mi][ni][q] = 0.f;

    uint32_t a_off = (uint32_t)((lane & 15) * A_PITCH + (lane >> 4) * 16);
    uint32_t b_off = (uint32_t)((lane & 15) * B_PITCH + (lane >> 4) * 16);

    load_stage(0, 0);
    load_stage(1, 64);

    for (int it = 0; it < NK; it++) {
        int s = it % 3;
        if (it + 1 < NK) asm volatile("cp.async.wait_group 1;" ::: "memory");
        else             asm volatile("cp.async.wait_group 0;" ::: "memory");
        __syncthreads();
        if (it + 2 < NK) load_stage((it + 2) % 3, (it + 2) * 64);

        uint32_t sA = sb0 + s * STG;
        uint32_t sB = sA + A_ARR;
        #pragma unroll
        for (int k16 = 0; k16 < 4; k16++) {
            uint32_t ah[2][4], bh[4][4];
            #pragma unroll
            for (int mi = 0; mi < 2; mi++)
                ldm_x4(ah[mi], sA + (WM + mi * 16) * A_PITCH + k16 * 32 + a_off);
            #pragma unroll
            for (int g = 0; g < 4; g++)
                ldm_x4_t(bh[g], sB + k16 * 16 * B_PITCH + (WN + g * 16) * 2 + b_off);
            #pragma unroll
            for (int mi = 0; mi < 2; mi++)
                #pragma unroll
                for (int g = 0; g < 4; g++) {
                    mma_f16(acc[mi][2 * g],     ah[mi], bh[g][0], bh[g][1]);
                    mma_f16(acc[mi][2 * g + 1], ah[mi], bh[g][2], bh[g][3]);
                }
        }
    }
    __syncthreads();

    // ---- epilogue via smem staging ----
    constexpr int EPITCH = 132;
    float* epi = (float*)smem;
    const float* bvec = bias + (size_t)e * NTOT + n0;
    float bscale = (ks == 0) ? 1.f : 0.f;   // bias added by split 0 only
    int g4 = lane >> 2, t4 = lane & 3;
    #pragma unroll
    for (int mi = 0; mi < 2; mi++) {
        int r0 = WM + mi * 16 + g4;
        float gate0 = 0.f, gate8 = 0.f;
        if (EPI == 2) {
            if (m0 + r0 < cnt)     gate0 = g_gates[e * T_TOK + m0 + r0];
            if (m0 + r0 + 8 < cnt) gate8 = g_gates[e * T_TOK + m0 + r0 + 8];
        }
        #pragma unroll
        for (int ni = 0; ni < 8; ni++) {
            int col = WN + ni * 8 + t4 * 2;
            float b0 = bvec[col] * bscale, b1 = bvec[col + 1] * bscale;
            float* a = acc[mi][ni];
            if (EPI == 1) {
                epi[r0 * EPITCH + col]           = fmaxf(a[0] + b0, 0.f);
                epi[r0 * EPITCH + col + 1]       = fmaxf(a[1] + b1, 0.f);
                epi[(r0 + 8) * EPITCH + col]     = fmaxf(a[2] + b0, 0.f);
                epi[(r0 + 8) * EPITCH + col + 1] = fmaxf(a[3] + b1, 0.f);
            } else {
                epi[r0 * EPITCH + col]           = (a[0] + b0) * gate0;
                epi[r0 * EPITCH + col + 1]       = (a[1] + b1) * gate0;
                epi[(r0 + 8) * EPITCH + col]     = (a[2] + b0) * gate8;
                epi[(r0 + 8) * EPITCH + col + 1] = (a[3] + b1) * gate8;
            }
        }
    }
    __syncthreads();

    if (EPI == 1) {
        f16* Hp = g_H + (size_t)(rowbase + m0) * F + n0;
        #pragma unroll
        for (int i = 0; i < 16; i++) {
            int c = tid + i * 256;
            int row = c >> 5, q = c & 31;
            float4 v = *(float4*)&epi[row * EPITCH + q * 4];
            f16 h[4];
            h[0] = __float2half_rn(v.x);
            h[1] = __float2half_rn(v.y);
            h[2] = __float2half_rn(v.z);
            h[3] = __float2half_rn(v.w);
            *(uint2*)&Hp[(size_t)row * F + q * 4] = *(uint2*)h;
        }
    } else {
        #pragma unroll
        for (int i = 0; i < 16; i++) {
            int c = tid + i * 256;
            int row = c >> 5, q = c & 31;
            if (m0 + row < cnt) {
                int tok = g_list[e * T_TOK + m0 + row];
                float4 v = *(float4*)&epi[row * EPITCH + q * 4];
                float* op = out + (size_t)tok * D + n0 + q * 4;
                atomicAdd(op + 0, v.x);
                atomicAdd(op + 1, v.y);
                atomicAdd(op + 2, v.z);
                atomicAdd(op + 3, v.w);
            }
        }
    }
}

#define SPLITK2 3

extern "C" void kernel_launch(void* const* d_in, const int* in_sizes, int n_in,
                              void* d_out, int out_size) {
    const float* x     = (const float*)d_in[0];
    const float* noise = (const float*)d_in[1];
    const float* Wg    = (const float*)d_in[2];
    const float* bg    = (const float*)d_in[3];
    const float* Wn    = (const float*)d_in[4];
    const float* bn    = (const float*)d_in[5];
    const float* W1    = (const float*)d_in[6];
    const float* b1    = (const float*)d_in[7];
    const float* W2    = (const float*)d_in[8];
    const float* b2    = (const float*)d_in[9];
    float* out = (float*)d_out;

    static bool attr_set = false;
    if (!attr_set) {
        cudaFuncSetAttribute(moe_gemm_mma<D, F, 1, 1>, cudaFuncAttributeMaxDynamicSharedMemorySize, SMEM_G);
        cudaFuncSetAttribute(moe_gemm_mma<F, D, 2, SPLITK2>, cudaFuncAttributeMaxDynamicSharedMemorySize, SMEM_G);
        attr_set = true;
    }

    cudaMemsetAsync(out, 0, (size_t)out_size * sizeof(float));
    init_kernel<<<1, 32>>>();
    router_kernel<<<T_TOK / 8, 256>>>(x, noise, Wg, bg, Wn, bn);
    finalize_kernel<<<1, 32>>>();
    gather_kernel<<<dim3(E, 256), 256>>>(x);
    conv_weights_kernel<<<4096, 256>>>(W1, 0);
    conv_weights_kernel<<<4096, 256>>>(W2, 1);
    moe_gemm_mma<D, F, 1, 1><<<dim3(F / 128, T_TOK / 128, E), 256, SMEM_G>>>(b1, out);
    moe_gemm_mma<F, D, 2, SPLITK2><<<dim3((D / 128) * SPLITK2, T_TOK / 128, E), 256, SMEM_G>>>(b2, out);
}

// round 11
// speedup vs baseline: 9.0691x; 1.0035x over previous
#include <cuda_runtime.h>
#include <cuda_fp16.h>
#include <math.h>
#include <stdint.h>

#define D 768
#define E 8
#define F 3072
#define T_TOK 4096
#define MAXROWS 10240

typedef __half f16;

__device__ int   g_counts[E];
__device__ int   g_off[E + 1];
__device__ int   g_list[E * T_TOK];
__device__ float g_gates[E * T_TOK];
__device__ f16   g_A[(size_t)MAXROWS * D];
__device__ f16   g_H[(size_t)MAXROWS * F];
__device__ f16   g_W1[(size_t)E * D * F];   // [E][D][F] native [k][n], fp16
__device__ f16   g_W2[(size_t)E * D * F];   // [E][F][D] native [k][n], fp16

__device__ __forceinline__ uint32_t smem_u32(const void* p) {
    uint32_t a;
    asm("{ .reg .u64 t; cvta.to.shared.u64 t, %1; cvt.u32.u64 %0, t; }" : "=r"(a) : "l"(p));
    return a;
}
__device__ __forceinline__ void cp16(uint32_t dst, const void* src) {
    asm volatile("cp.async.cg.shared.global [%0], [%1], 16;"
                 :: "r"(dst), "l"(__cvta_generic_to_global(src)));
}
#define CP_COMMIT() asm volatile("cp.async.commit_group;" ::: "memory")

__device__ __forceinline__ void ldm_x4(uint32_t* r, uint32_t addr) {
    asm volatile("ldmatrix.sync.aligned.m8n8.x4.shared.b16 {%0,%1,%2,%3}, [%4];"
                 : "=r"(r[0]), "=r"(r[1]), "=r"(r[2]), "=r"(r[3]) : "r"(addr));
}
__device__ __forceinline__ void ldm_x4_t(uint32_t* r, uint32_t addr) {
    asm volatile("ldmatrix.sync.aligned.m8n8.x4.trans.shared.b16 {%0,%1,%2,%3}, [%4];"
                 : "=r"(r[0]), "=r"(r[1]), "=r"(r[2]), "=r"(r[3]) : "r"(addr));
}
__device__ __forceinline__ void mma_f16(float* c, const uint32_t* a, uint32_t b0, uint32_t b1) {
    asm volatile("mma.sync.aligned.m16n8k16.row.col.f32.f16.f16.f32 "
                 "{%0,%1,%2,%3}, {%4,%5,%6,%7}, {%8,%9}, {%0,%1,%2,%3};"
                 : "+f"(c[0]), "+f"(c[1]), "+f"(c[2]), "+f"(c[3])
                 : "r"(a[0]), "r"(a[1]), "r"(a[2]), "r"(a[3]), "r"(b0), "r"(b1));
}

__global__ void init_kernel() { if (threadIdx.x < E) g_counts[threadIdx.x] = 0; }

// warp-per-token router: 8 tokens per 256-thread block, Wg/Wn staged transposed in smem.
#define WPITCH 776
__global__ void __launch_bounds__(256) router_kernel(
        const float* __restrict__ x, const float* __restrict__ noise,
        const float* __restrict__ Wg, const float* __restrict__ bg,
        const float* __restrict__ Wn, const float* __restrict__ bn) {
    __shared__ float wg[E * WPITCH];
    __shared__ float wn[E * WPITCH];
    int tid = threadIdx.x, lane = tid & 31, w = tid >> 5;
    for (int i = tid; i < D * E; i += 256) {
        int d = i >> 3, e = i & 7;
        wg[e * WPITCH + d] = Wg[i];
        wn[e * WPITCH + d] = Wn[i];
    }
    __syncthreads();

    int t = blockIdx.x * 8 + w;
    const float* xr = x + (size_t)t * D;
    float xv[D / 32];
    #pragma unroll
    for (int i = 0; i < D / 32; i++) xv[i] = xr[i * 32 + lane];

    float sg[E], sn[E];
    #pragma unroll
    for (int e = 0; e < E; e++) { sg[e] = 0.f; sn[e] = 0.f; }
    #pragma unroll
    for (int i = 0; i < D / 32; i++) {
        int d = i * 32 + lane;
        #pragma unroll
        for (int e = 0; e < E; e++) {
            sg[e] = fmaf(xv[i], wg[e * WPITCH + d], sg[e]);
            sn[e] = fmaf(xv[i], wn[e * WPITCH + d], sn[e]);
        }
    }
    #pragma unroll
    for (int e = 0; e < E; e++) {
        #pragma unroll
        for (int o = 16; o > 0; o >>= 1) {
            sg[e] += __shfl_xor_sync(~0u, sg[e], o);
            sn[e] += __shfl_xor_sync(~0u, sn[e], o);
        }
    }
    if (lane == 0) {
        float noisy[E];
        #pragma unroll
        for (int e = 0; e < E; e++) {
            float lg = sg[e] + bg[e], ln = sn[e] + bn[e];
            float sp = (ln > 20.f) ? ln : log1pf(expf(ln));
            noisy[e] = lg + noise[(size_t)t * E + e] * sp;
        }
        int i1 = 0; float v1 = noisy[0];
        #pragma unroll
        for (int e = 1; e < E; e++) if (noisy[e] > v1) { v1 = noisy[e]; i1 = e; }
        int i2 = -1; float v2 = -3.4e38f;
        #pragma unroll
        for (int e = 0; e < E; e++) {
            if (e == i1) continue;
            if (noisy[e] > v2) { v2 = noisy[e]; i2 = e; }
        }
        float eb = expf(v2 - v1);
        float p1 = 1.f / (1.f + eb), p2 = eb / (1.f + eb);
        if (p1 > 1e-9f) {
            int pos = atomicAdd(&g_counts[i1], 1);
            g_list[i1 * T_TOK + pos] = t; g_gates[i1 * T_TOK + pos] = p1;
        }
        if (p2 > 1e-9f) {
            int pos = atomicAdd(&g_counts[i2], 1);
            g_list[i2 * T_TOK + pos] = t; g_gates[i2 * T_TOK + pos] = p2;
        }
    }
}

__global__ void finalize_kernel() {
    if (threadIdx.x == 0) {
        int off = 0;
        for (int e = 0; e < E; e++) { g_off[e] = off; off += (g_counts[e] + 127) & ~127; }
        g_off[E] = off;
    }
}

__global__ void __launch_bounds__(256) gather_kernel(const float* __restrict__ x) {
    int e = blockIdx.x;
    int cnt = g_counts[e], pad = (cnt + 127) & ~127;
    int rb = blockIdx.y * 16;
    if (rb >= pad) return;
    int base = g_off[e];
    const int Q = D / 4;
    for (int idx = threadIdx.x; idx < 16 * Q; idx += 256) {
        int m = rb + idx / Q, q = idx % Q;
        float4 v = make_float4(0.f, 0.f, 0.f, 0.f);
        if (m < cnt)
            v = *(const float4*)&x[(size_t)g_list[e * T_TOK + m] * D + q * 4];
        f16 h[4];
        h[0] = __float2half_rn(v.x);
        h[1] = __float2half_rn(v.y);
        h[2] = __float2half_rn(v.z);
        h[3] = __float2half_rn(v.w);
        *(uint2*)&g_A[(size_t)(base + m) * D + q * 4] = *(uint2*)h;
    }
}

__global__ void __launch_bounds__(256) conv_weights_kernel(const float* __restrict__ W, int which) {
    f16* Th = which ? g_W2 : g_W1;
    const size_t n4 = (size_t)E * D * F / 4;
    size_t stride = (size_t)gridDim.x * blockDim.x;
    for (size_t i = (size_t)blockIdx.x * blockDim.x + threadIdx.x; i < n4; i += stride) {
        float4 v = *(const float4*)&W[i * 4];
        f16 h[4];
        h[0] = __float2half_rn(v.x);
        h[1] = __float2half_rn(v.y);
        h[2] = __float2half_rn(v.z);
        h[3] = __float2half_rn(v.w);
        *(uint2*)&Th[i * 4] = *(uint2*)h;
    }
}

// ------------- pure fp16 mma.sync GEMM, optional split-K -------------
// CTA 128 x 128, K-step 64, 3 smem stages, 8 warps (4M x 2N, warp 32x64), 2 CTAs/SM.
#define A_PITCH 144
#define A_ARR   18432
#define B_PITCH 272
#define B_ARR   17408
#define STG     35840
#define SMEM_G  107520    // 3 stages

template<int KTOT, int NTOT, int EPI, int SPLITK>
__global__ void __launch_bounds__(256, 2) moe_gemm_mma(const float* __restrict__ bias,
                                                       float* __restrict__ out) {
    constexpr int KLOC = KTOT / SPLITK;
    constexpr int NK   = KLOC / 64;

    int e = blockIdx.z, cnt = g_counts[e];
    int m0 = blockIdx.y * 128;
    int pad = (cnt + 127) & ~127;
    if (m0 >= pad) return;
    int nt = blockIdx.x / SPLITK;
    int ks = blockIdx.x % SPLITK;
    int n0 = nt * 128, rowbase = g_off[e];
    int kbase = ks * KLOC;

    extern __shared__ __align__(1024) char smem[];
    uint32_t sb0 = smem_u32(smem);
    int tid = threadIdx.x, wid = tid >> 5, lane = tid & 31;
    int WM = (wid >> 1) * 32;
    int WN = (wid & 1) * 64;

    const f16* Ag = (EPI == 1 ? g_A : g_H) + (size_t)(rowbase + m0) * KTOT + kbase;
    const f16* Bg = (EPI == 1 ? g_W1 : g_W2) + (size_t)e * D * F + (size_t)kbase * NTOT + n0;

    auto load_stage = [&](int s, int k0) {
        uint32_t sb = sb0 + s * STG;
        #pragma unroll
        for (int i = 0; i < 8; i++) {
            int c = tid + i * 256;
            if (c < 1024) {
                int row = c >> 3, ch = c & 7;
                cp16(sb + row * A_PITCH + ch * 16,
                     Ag + (size_t)row * KTOT + k0 + ch * 8);
            } else {
                int cb = c - 1024, row = cb >> 4, ch = cb & 15;
                cp16(sb + A_ARR + row * B_PITCH + ch * 16,
                     Bg + (size_t)(k0 + row) * NTOT + ch * 8);
            }
        }
        CP_COMMIT();
    };

    float acc[2][8][4];
    #pragma unroll
    for (int mi = 0; mi < 2; mi++)
        #pragma unroll
        for (int ni = 0; ni < 8; ni++)
            #pragma unroll
            for (int q = 0; q < 4; q++) acc[mi][ni][q] = 0.f;

    uint32_t a_off = (uint32_t)((lane & 15) * A_PITCH + (lane >> 4) * 16);
    uint32_t b_off = (uint32_t)((lane & 15) * B_PITCH + (lane >> 4) * 16);

    load_stage(0, 0);
    load_stage(1, 64);

    for (int it = 0; it < NK; it++) {
        int s = it % 3;
        if (it + 1 < NK) asm volatile("cp.async.wait_group 1;" ::: "memory");
        else             asm volatile("cp.async.wait_group 0;" ::: "memory");
        __syncthreads();
        if (it + 2 < NK) load_stage((it + 2) % 3, (it + 2) * 64);

        uint32_t sA = sb0 + s * STG;
        uint32_t sB = sA + A_ARR;
        #pragma unroll
        for (int k16 = 0; k16 < 4; k16++) {
            uint32_t ah[2][4], bh[4][4];
            #pragma unroll
            for (int mi = 0; mi < 2; mi++)
                ldm_x4(ah[mi], sA + (WM + mi * 16) * A_PITCH + k16 * 32 + a_off);
            #pragma unroll
            for (int g = 0; g < 4; g++)
                ldm_x4_t(bh[g], sB + k16 * 16 * B_PITCH + (WN + g * 16) * 2 + b_off);
            #pragma unroll
            for (int mi = 0; mi < 2; mi++)
                #pragma unroll
                for (int g = 0; g < 4; g++) {
                    mma_f16(acc[mi][2 * g],     ah[mi], bh[g][0], bh[g][1]);
                    mma_f16(acc[mi][2 * g + 1], ah[mi], bh[g][2], bh[g][3]);
                }
        }
    }
    __syncthreads();

    // ---- epilogue via smem staging ----
    constexpr int EPITCH = 132;
    float* epi = (float*)smem;
    const float* bvec = bias + (size_t)e * NTOT + n0;
    float bscale = (ks == 0) ? 1.f : 0.f;
    int g4 = lane >> 2, t4 = lane & 3;
    #pragma unroll
    for (int mi = 0; mi < 2; mi++) {
        int r0 = WM + mi * 16 + g4;
        float gate0 = 0.f, gate8 = 0.f;
        if (EPI == 2) {
            if (m0 + r0 < cnt)     gate0 = g_gates[e * T_TOK + m0 + r0];
            if (m0 + r0 + 8 < cnt) gate8 = g_gates[e * T_TOK + m0 + r0 + 8];
        }
        #pragma unroll
        for (int ni = 0; ni < 8; ni++) {
            int col = WN + ni * 8 + t4 * 2;
            float b0 = bvec[col] * bscale, b1 = bvec[col + 1] * bscale;
            float* a = acc[mi][ni];
            if (EPI == 1) {
                epi[r0 * EPITCH + col]           = fmaxf(a[0] + b0, 0.f);
                epi[r0 * EPITCH + col + 1]       = fmaxf(a[1] + b1, 0.f);
                epi[(r0 + 8) * EPITCH + col]     = fmaxf(a[2] + b0, 0.f);
                epi[(r0 + 8) * EPITCH + col + 1] = fmaxf(a[3] + b1, 0.f);
            } else {
                epi[r0 * EPITCH + col]           = (a[0] + b0) * gate0;
                epi[r0 * EPITCH + col + 1]       = (a[1] + b1) * gate0;
                epi[(r0 + 8) * EPITCH + col]     = (a[2] + b0) * gate8;
                epi[(r0 + 8) * EPITCH + col + 1] = (a[3] + b1) * gate8;
            }
        }
    }
    __syncthreads();

    if (EPI == 1) {
        f16* Hp = g_H + (size_t)(rowbase + m0) * F + n0;
        #pragma unroll
        for (int i = 0; i < 16; i++) {
            int c = tid + i * 256;
            int row = c >> 5, q = c & 31;
            float4 v = *(float4*)&epi[row * EPITCH + q * 4];
            f16 h[4];
            h[0] = __float2half_rn(v.x);
            h[1] = __float2half_rn(v.y);
            h[2] = __float2half_rn(v.z);
            h[3] = __float2half_rn(v.w);
            *(uint2*)&Hp[(size_t)row * F + q * 4] = *(uint2*)h;
        }
    } else {
        #pragma unroll
        for (int i = 0; i < 16; i++) {
            int c = tid + i * 256;
            int row = c >> 5, q = c & 31;
            if (m0 + row < cnt) {
                int tok = g_list[e * T_TOK + m0 + row];
                float4 v = *(float4*)&epi[row * EPITCH + q * 4];
                float* op = out + (size_t)tok * D + n0 + q * 4;
                atomicAdd(op + 0, v.x);
                atomicAdd(op + 1, v.y);
                atomicAdd(op + 2, v.z);
                atomicAdd(op + 3, v.w);
            }
        }
    }
}

#define SPLITK2 3

extern "C" void kernel_launch(void* const* d_in, const int* in_sizes, int n_in,
                              void* d_out, int out_size) {
    const float* x     = (const float*)d_in[0];
    const float* noise = (const float*)d_in[1];
    const float* Wg    = (const float*)d_in[2];
    const float* bg    = (const float*)d_in[3];
    const float* Wn    = (const float*)d_in[4];
    const float* bn    = (const float*)d_in[5];
    const float* W1    = (const float*)d_in[6];
    const float* b1    = (const float*)d_in[7];
    const float* W2    = (const float*)d_in[8];
    const float* b2    = (const float*)d_in[9];
    float* out = (float*)d_out;

    static cudaStream_t s2 = nullptr;
    static cudaEvent_t evFork = nullptr, evW1 = nullptr, evW2 = nullptr;
    static bool init_done = false;
    if (!init_done) {
        cudaFuncSetAttribute(moe_gemm_mma<D, F, 1, 1>, cudaFuncAttributeMaxDynamicSharedMemorySize, SMEM_G);
        cudaFuncSetAttribute(moe_gemm_mma<F, D, 2, SPLITK2>, cudaFuncAttributeMaxDynamicSharedMemorySize, SMEM_G);
        cudaStreamCreateWithFlags(&s2, cudaStreamNonBlocking);
        cudaEventCreateWithFlags(&evFork, cudaEventDisableTiming);
        cudaEventCreateWithFlags(&evW1, cudaEventDisableTiming);
        cudaEventCreateWithFlags(&evW2, cudaEventDisableTiming);
        init_done = true;
    }

    // fork: weight conversions on s2, concurrent with router/gather chain
    cudaEventRecord(evFork, 0);
    cudaStreamWaitEvent(s2, evFork, 0);
    conv_weights_kernel<<<4096, 256, 0, s2>>>(W1, 0);
    cudaEventRecord(evW1, s2);
    conv_weights_kernel<<<4096, 256, 0, s2>>>(W2, 1);
    cudaEventRecord(evW2, s2);

    // main stream: routing + gather
    cudaMemsetAsync(out, 0, (size_t)out_size * sizeof(float));
    init_kernel<<<1, 32>>>();
    router_kernel<<<T_TOK / 8, 256>>>(x, noise, Wg, bg, Wn, bn);
    finalize_kernel<<<1, 32>>>();
    gather_kernel<<<dim3(E, 256), 256>>>(x);

    // join W1 before GEMM1, W2 before GEMM2
    cudaStreamWaitEvent(0, evW1, 0);
    moe_gemm_mma<D, F, 1, 1><<<dim3(F / 128, T_TOK / 128, E), 256, SMEM_G>>>(b1, out);
    cudaStreamWaitEvent(0, evW2, 0);
    moe_gemm_mma<F, D, 2, SPLITK2><<<dim3((D / 128) * SPLITK2, T_TOK / 128, E), 256, SMEM_G>>>(b2, out);
}